// round 11
// baseline (speedup 1.0000x reference)
#include <cuda_runtime.h>
#include <cstdint>

#define CIN   32
#define COUT  64
#define EPS   1e-4f
#define LEAK  0.333f

#define HB           256
#define N_MAX        1600000
#define CONV_BLOCKS  592           // 148 SMs * 4 blocks of 128
#define STATS_BLOCKS 1184

__device__ int   g_blockhist[4 * HB];
__device__ int   g_blockoff[4 * HB];
__device__ int   g_bucket_start[5];
__device__ int   g_perm[N_MAX];
__device__ float g_partials[STATS_BLOCKS * 128];
__device__ float g_tot[128];
__device__ float g_coef[128];

// ---- packed f32x2 helpers (sm_103a) ---------------------------------------
__device__ __forceinline__ unsigned long long packpair(float lo, float hi) {
    unsigned long long r;
    asm("mov.b64 %0, {%1, %2};" : "=l"(r) : "f"(lo), "f"(hi));
    return r;
}
__device__ __forceinline__ unsigned long long ffma2(unsigned long long a,
                                                    unsigned long long b,
                                                    unsigned long long c) {
    unsigned long long d;
    asm("fma.rn.f32x2 %0, %1, %2, %3;" : "=l"(d) : "l"(a), "l"(b), "l"(c));
    return d;
}
__device__ __forceinline__ void unpack2(unsigned long long v, float& lo, float& hi) {
    asm("mov.b64 {%0, %1}, %2;" : "=f"(lo), "=f"(hi) : "l"(v));
}

// ---- sort pass 1: per-block histogram of kern_idx --------------------------
__global__ __launch_bounds__(256) void hist_kernel(const int* __restrict__ kern_idx,
                                                   int n_rows)
{
    __shared__ int cnt[4];
    if (threadIdx.x < 4) cnt[threadIdx.x] = 0;
    __syncthreads();
    int chunk = (n_rows + HB - 1) / HB;
    int i0 = blockIdx.x * chunk;
    int i1 = min(i0 + chunk, n_rows);
    int c[4] = {0, 0, 0, 0};
    for (int i = i0 + threadIdx.x; i < i1; i += 256) c[kern_idx[i]]++;
    #pragma unroll
    for (int kk = 0; kk < 4; kk++)
        if (c[kk]) atomicAdd(&cnt[kk], c[kk]);
    __syncthreads();
    if (threadIdx.x < 4)
        g_blockhist[threadIdx.x * HB + blockIdx.x] = cnt[threadIdx.x];
}

// ---- sort pass 2: segmented scan -> per-block offsets + bucket starts ------
__global__ void scan_kernel(int n_rows)
{
    __shared__ int sh[4 * HB];
    int t = threadIdx.x;            // 0..1023, t = k*256 + b
    int orig = g_blockhist[t];
    sh[t] = orig;
    __syncthreads();
    for (int s = 1; s < HB; s <<= 1) {
        int add = ((t & (HB - 1)) >= s) ? sh[t - s] : 0;
        __syncthreads();
        sh[t] += add;
        __syncthreads();
    }
    int k = t >> 8;
    int kbase = 0;
    for (int kk = 0; kk < k; kk++) kbase += sh[kk * HB + HB - 1];
    g_blockoff[t] = kbase + (sh[t] - orig);
    if ((t & (HB - 1)) == 0) g_bucket_start[k] = kbase;
    if (t == 0) g_bucket_start[4] = n_rows;
}

// ---- sort pass 3: scatter row indices into buckets -------------------------
__global__ __launch_bounds__(256) void scatter_kernel(const int* __restrict__ kern_idx,
                                                      int n_rows)
{
    __shared__ int scur[4];
    if (threadIdx.x < 4)
        scur[threadIdx.x] = g_blockoff[threadIdx.x * HB + blockIdx.x];
    __syncthreads();
    int chunk = (n_rows + HB - 1) / HB;
    int i0 = blockIdx.x * chunk;
    int i1 = min(i0 + chunk, n_rows);
    int iters = (i1 > i0) ? ((i1 - i0 + 255) >> 8) : 0;
    int lane = threadIdx.x & 31;
    for (int it = 0; it < iters; it++) {
        int i = i0 + it * 256 + threadIdx.x;
        int k = (i < i1) ? kern_idx[i] : -1;
        #pragma unroll
        for (int kk = 0; kk < 4; kk++) {
            unsigned mask = __ballot_sync(0xFFFFFFFFu, k == kk);
            if (k == kk) {
                int leader = __ffs(mask) - 1;
                int base = 0;
                if (lane == leader) base = atomicAdd(&scur[kk], __popc(mask));
                base = __shfl_sync(mask, base, leader);
                int pos = base + __popc(mask & ((1u << lane) - 1));
                g_perm[pos] = i;
            }
        }
    }
}

// ---- conv: warp-per-4-ROWS, j-pair packed weights in regs ------------------
// lane l owns channels {2l,2l+1}. Per iteration (4 rows): 1 LDGSTS (16B/lane,
// all 4 rows), 32 broadcast LDS.128, 128 FFMA2 in 8 independent chains,
// 4 RED.64. One wait/sync per 4 rows.
__global__ __launch_bounds__(128, 4) void conv_scatter(
    const float* __restrict__ feat,
    const float* __restrict__ weight,
    const int*   __restrict__ out_idx,
    float*       __restrict__ out)
{
    __shared__ ulonglong2 ring[4][4][32];   // [warp][stage][4 rows x 8] = 8KB
    int lane   = threadIdx.x & 31;
    int wlocal = threadIdx.x >> 5;
    int gw     = (blockIdx.x * blockDim.x + threadIdx.x) >> 5;
    int k      = gw & 3;
    int wslot  = gw >> 2;
    int nwb    = (gridDim.x * blockDim.x) >> 7;   // warps per bucket

    // j-pair packed weights for lane's two channels
    int c0 = 2 * lane;
    unsigned long long w0[16], w1[16];
    #pragma unroll
    for (int u = 0; u < 16; u++) {
        const float* r0p = weight + (size_t)(k * 32 + 2 * u) * COUT;
        const float* r1p = weight + (size_t)(k * 32 + 2 * u + 1) * COUT;
        w0[u] = packpair(r0p[c0],     r1p[c0]);
        w1[u] = packpair(r0p[c0 + 1], r1p[c0 + 1]);
    }

    int start = g_bucket_start[k];
    int end   = g_bucket_start[k + 1];
    if (start >= end) return;

    int p0 = start + wslot;

    // row for step j is g_perm[p0 + j*nwb]; iteration m covers j=4m..4m+3
    int ii[12];                                // steps 4m .. 4m+11
    #pragma unroll
    for (int j = 0; j < 12; j++) {
        int pc = p0 + j * nwb;
        pc = pc < end ? pc : end - 1;
        ii[j] = g_perm[pc];
    }
    int oq[8];                                 // out rows, iterations m, m+1
    #pragma unroll
    for (int j = 0; j < 8; j++) oq[j] = out_idx[ii[j]];

    unsigned sbase = (unsigned)__cvta_generic_to_shared(&ring[wlocal][0][0]);
    int rsel = lane >> 3;                      // which of 4 rows this lane fills
    int foff = (lane & 7) * 4;                 // float offset within row (16B chunks)

    // prologue: fill stages 0..2 (iterations 0,1,2)
    #pragma unroll
    for (int s = 0; s < 3; s++) {
        int row = rsel == 0 ? ii[4 * s]     : rsel == 1 ? ii[4 * s + 1]
                : rsel == 2 ? ii[4 * s + 2] : ii[4 * s + 3];
        const float* g = feat + (size_t)row * CIN + foff;
        asm volatile("cp.async.ca.shared.global [%0], [%1], 16;"
                     :: "r"(sbase + s * 512 + lane * 16), "l"(g));
        asm volatile("cp.async.commit_group;");
    }

    int m = 0;
    for (int p = p0; p < end; p += 4 * nwb, m++) {
        // perm rows for iteration m+3 (steps 4m+12..15), clamped
        int pa = p + 12 * nwb; pa = pa < end ? pa : end - 1;
        int pb = p + 13 * nwb; pb = pb < end ? pb : end - 1;
        int pc = p + 14 * nwb; pc = pc < end ? pc : end - 1;
        int pd = p + 15 * nwb; pd = pd < end ? pd : end - 1;
        int na = g_perm[pa], nb = g_perm[pb], nc = g_perm[pc], nd = g_perm[pd];
        // out rows for iteration m+2
        int oa = out_idx[ii[8]],  ob = out_idx[ii[9]];
        int oc = out_idx[ii[10]], od = out_idx[ii[11]];

        // fill stage for iteration m+3 with freshly loaded rows
        {
            int row = rsel == 0 ? na : rsel == 1 ? nb : rsel == 2 ? nc : nd;
            int s = (m + 3) & 3;
            const float* g = feat + (size_t)row * CIN + foff;
            asm volatile("cp.async.ca.shared.global [%0], [%1], 16;"
                         :: "r"(sbase + s * 512 + lane * 16), "l"(g));
            asm volatile("cp.async.commit_group;");
        }
        asm volatile("cp.async.wait_group 3;");
        __syncwarp();

        const ulonglong2* q = ring[wlocal][m & 3];
        // 8 independent chains: (A,B) per row
        unsigned long long A0 = 0, B0 = 0, A1 = 0, B1 = 0;
        unsigned long long A2 = 0, B2 = 0, A3 = 0, B3 = 0;
        #pragma unroll
        for (int t = 0; t < 8; t++) {
            ulonglong2 q0 = q[t], q1 = q[8 + t], q2 = q[16 + t], q3 = q[24 + t];
            A0 = ffma2(w0[2 * t], q0.x, A0);
            B0 = ffma2(w1[2 * t], q0.x, B0);
            A1 = ffma2(w0[2 * t], q1.x, A1);
            B1 = ffma2(w1[2 * t], q1.x, B1);
            A2 = ffma2(w0[2 * t], q2.x, A2);
            B2 = ffma2(w1[2 * t], q2.x, B2);
            A3 = ffma2(w0[2 * t], q3.x, A3);
            B3 = ffma2(w1[2 * t], q3.x, B3);
            A0 = ffma2(w0[2 * t + 1], q0.y, A0);
            B0 = ffma2(w1[2 * t + 1], q0.y, B0);
            A1 = ffma2(w0[2 * t + 1], q1.y, A1);
            B1 = ffma2(w1[2 * t + 1], q1.y, B1);
            A2 = ffma2(w0[2 * t + 1], q2.y, A2);
            B2 = ffma2(w1[2 * t + 1], q2.y, B2);
            A3 = ffma2(w0[2 * t + 1], q3.y, A3);
            B3 = ffma2(w1[2 * t + 1], q3.y, B3);
        }
        float xa, xb, ya, yb;
        unpack2(A0, xa, xb); unpack2(B0, ya, yb);
        atomicAdd(reinterpret_cast<float2*>(out + (size_t)oq[0] * COUT + c0),
                  make_float2(xa + xb, ya + yb));
        if (p + 1 * nwb < end) {
            unpack2(A1, xa, xb); unpack2(B1, ya, yb);
            atomicAdd(reinterpret_cast<float2*>(out + (size_t)oq[1] * COUT + c0),
                      make_float2(xa + xb, ya + yb));
        }
        if (p + 2 * nwb < end) {
            unpack2(A2, xa, xb); unpack2(B2, ya, yb);
            atomicAdd(reinterpret_cast<float2*>(out + (size_t)oq[2] * COUT + c0),
                      make_float2(xa + xb, ya + yb));
        }
        if (p + 3 * nwb < end) {
            unpack2(A3, xa, xb); unpack2(B3, ya, yb);
            atomicAdd(reinterpret_cast<float2*>(out + (size_t)oq[3] * COUT + c0),
                      make_float2(xa + xb, ya + yb));
        }

        // rotate queues by one iteration (4 entries)
        ii[0] = ii[4];  ii[1] = ii[5];  ii[2] = ii[6];  ii[3] = ii[7];
        ii[4] = ii[8];  ii[5] = ii[9];  ii[6] = ii[10]; ii[7] = ii[11];
        ii[8] = na;     ii[9] = nb;     ii[10] = nc;    ii[11] = nd;
        oq[0] = oq[4];  oq[1] = oq[5];  oq[2] = oq[6];  oq[3] = oq[7];
        oq[4] = oa;     oq[5] = ob;     oq[6] = oc;     oq[7] = od;
    }
    asm volatile("cp.async.wait_group 0;");   // drain before exit
}

// ---- stats: per-channel sum / sumsq partials -------------------------------
__global__ __launch_bounds__(256) void stats_kernel(const float* __restrict__ out,
                                                    int n_out)
{
    __shared__ float sh[128];
    if (threadIdx.x < 128) sh[threadIdx.x] = 0.f;
    __syncthreads();

    int gid = blockIdx.x * blockDim.x + threadIdx.x;
    int c4 = threadIdx.x & 15;
    int row0 = gid >> 4;
    int rstride = (gridDim.x * blockDim.x) >> 4;
    const float4* o4 = reinterpret_cast<const float4*>(out);

    float4 s = make_float4(0.f, 0.f, 0.f, 0.f);
    float4 q = make_float4(0.f, 0.f, 0.f, 0.f);
    for (int r = row0; r < n_out; r += rstride) {
        float4 v = o4[(size_t)r * 16 + c4];
        s.x += v.x; s.y += v.y; s.z += v.z; s.w += v.w;
        q.x += v.x * v.x; q.y += v.y * v.y; q.z += v.z * v.z; q.w += v.w * v.w;
    }
    s.x += __shfl_down_sync(0xFFFFFFFFu, s.x, 16);
    s.y += __shfl_down_sync(0xFFFFFFFFu, s.y, 16);
    s.z += __shfl_down_sync(0xFFFFFFFFu, s.z, 16);
    s.w += __shfl_down_sync(0xFFFFFFFFu, s.w, 16);
    q.x += __shfl_down_sync(0xFFFFFFFFu, q.x, 16);
    q.y += __shfl_down_sync(0xFFFFFFFFu, q.y, 16);
    q.z += __shfl_down_sync(0xFFFFFFFFu, q.z, 16);
    q.w += __shfl_down_sync(0xFFFFFFFFu, q.w, 16);

    if ((threadIdx.x & 31) < 16) {
        atomicAdd(&sh[c4 * 4 + 0], s.x);
        atomicAdd(&sh[c4 * 4 + 1], s.y);
        atomicAdd(&sh[c4 * 4 + 2], s.z);
        atomicAdd(&sh[c4 * 4 + 3], s.w);
        atomicAdd(&sh[64 + c4 * 4 + 0], q.x);
        atomicAdd(&sh[64 + c4 * 4 + 1], q.y);
        atomicAdd(&sh[64 + c4 * 4 + 2], q.z);
        atomicAdd(&sh[64 + c4 * 4 + 3], q.w);
    }
    __syncthreads();
    if (threadIdx.x < 128)
        g_partials[blockIdx.x * 128 + threadIdx.x] = sh[threadIdx.x];
}

// ---- reduce partials (parallel over 128 stat slots) ------------------------
__global__ __launch_bounds__(256) void reduce_kernel()
{
    int s = blockIdx.x;                 // 0..127
    float acc = 0.f;
    for (int b = threadIdx.x; b < STATS_BLOCKS; b += 256)
        acc += g_partials[b * 128 + s];
    __shared__ float sh[256];
    sh[threadIdx.x] = acc;
    __syncthreads();
    for (int st = 128; st > 0; st >>= 1) {
        if (threadIdx.x < st) sh[threadIdx.x] += sh[threadIdx.x + st];
        __syncthreads();
    }
    if (threadIdx.x == 0) g_tot[s] = sh[0];
}

// ---- coef: per-channel A,B -------------------------------------------------
__global__ void coef2_kernel(const float* __restrict__ gamma,
                             const float* __restrict__ beta,
                             int n_out)
{
    int t = threadIdx.x;   // 0..63
    float inv_n = 1.0f / (float)n_out;
    float mean = g_tot[t] * inv_n;
    float var  = g_tot[64 + t] * inv_n - mean * mean;
    float A = gamma[t] * rsqrtf(var + EPS);
    g_coef[t] = A;
    g_coef[64 + t] = beta[t] - mean * A;
}

// ---- norm + leaky relu (in place, at DRAM roofline) ------------------------
__global__ __launch_bounds__(256) void norm_kernel(float* __restrict__ out, int n_out)
{
    int gid = blockIdx.x * blockDim.x + threadIdx.x;
    int c4 = threadIdx.x & 15;
    const float4* cf = reinterpret_cast<const float4*>(g_coef);
    float4 A = cf[c4];
    float4 B = cf[16 + c4];
    int row0 = gid >> 4;
    int rstride = (gridDim.x * blockDim.x) >> 4;
    float4* o4 = reinterpret_cast<float4*>(out);
    for (int r = row0; r < n_out; r += rstride) {
        size_t idx = (size_t)r * 16 + c4;
        float4 v = o4[idx];
        float4 y;
        y.x = fmaf(v.x, A.x, B.x);
        y.y = fmaf(v.y, A.y, B.y);
        y.z = fmaf(v.z, A.z, B.z);
        y.w = fmaf(v.w, A.w, B.w);
        y.x = fmaxf(y.x, LEAK * y.x);
        y.y = fmaxf(y.y, LEAK * y.y);
        y.z = fmaxf(y.z, LEAK * y.z);
        y.w = fmaxf(y.w, LEAK * y.w);
        o4[idx] = y;
    }
}

// ---- launch ----------------------------------------------------------------
extern "C" void kernel_launch(void* const* d_in, const int* in_sizes, int n_in,
                              void* d_out, int out_size)
{
    const float* feat    = (const float*)d_in[0];
    const float* weight  = (const float*)d_in[1];
    // d_in[2] = bias: cancelled exactly by BN mean subtraction
    const float* gamma   = (const float*)d_in[3];
    const float* beta    = (const float*)d_in[4];
    const int*   out_idx = (const int*)d_in[5];
    const int*   kern_idx= (const int*)d_in[6];
    int n_rows = in_sizes[0] / CIN;
    int n_out  = out_size / COUT;
    float* out = (float*)d_out;

    cudaMemsetAsync(d_out, 0, (size_t)out_size * sizeof(float));
    hist_kernel<<<HB, 256>>>(kern_idx, n_rows);
    scan_kernel<<<1, 4 * HB>>>(n_rows);
    scatter_kernel<<<HB, 256>>>(kern_idx, n_rows);
    conv_scatter<<<CONV_BLOCKS, 128>>>(feat, weight, out_idx, out);  // 5th launch -> ncu slot
    stats_kernel<<<STATS_BLOCKS, 256>>>(out, n_out);
    reduce_kernel<<<128, 256>>>();
    coef2_kernel<<<1, 64>>>(gamma, beta, n_out);
    norm_kernel<<<1184, 256>>>(out, n_out);
}

// round 12
// speedup vs baseline: 1.1303x; 1.1303x over previous
#include <cuda_runtime.h>
#include <cstdint>

#define CIN   32
#define COUT  64
#define EPS   1e-4f
#define LEAK  0.333f

#define HB           256
#define N_MAX        1600000
#define CONV_BLOCKS  888           // 148 SMs * 6 blocks of 128
#define STATS_BLOCKS 1184

__device__ int   g_blockhist[4 * HB];
__device__ int   g_blockoff[4 * HB];
__device__ int   g_bucket_start[5];
__device__ int   g_perm[N_MAX];
__device__ float g_partials[STATS_BLOCKS * 128];
__device__ float g_tot[128];
__device__ float g_coef[128];

// ---- packed f32x2 helpers (sm_103a) ---------------------------------------
__device__ __forceinline__ unsigned long long packpair(float lo, float hi) {
    unsigned long long r;
    asm("mov.b64 %0, {%1, %2};" : "=l"(r) : "f"(lo), "f"(hi));
    return r;
}
__device__ __forceinline__ unsigned long long ffma2(unsigned long long a,
                                                    unsigned long long b,
                                                    unsigned long long c) {
    unsigned long long d;
    asm("fma.rn.f32x2 %0, %1, %2, %3;" : "=l"(d) : "l"(a), "l"(b), "l"(c));
    return d;
}
__device__ __forceinline__ void unpack2(unsigned long long v, float& lo, float& hi) {
    asm("mov.b64 {%0, %1}, %2;" : "=f"(lo), "=f"(hi) : "l"(v));
}

// ---- sort pass 1: per-block histogram of kern_idx --------------------------
__global__ __launch_bounds__(256) void hist_kernel(const int* __restrict__ kern_idx,
                                                   int n_rows)
{
    __shared__ int cnt[4];
    if (threadIdx.x < 4) cnt[threadIdx.x] = 0;
    __syncthreads();
    int chunk = (n_rows + HB - 1) / HB;
    int i0 = blockIdx.x * chunk;
    int i1 = min(i0 + chunk, n_rows);
    int c[4] = {0, 0, 0, 0};
    for (int i = i0 + threadIdx.x; i < i1; i += 256) c[kern_idx[i]]++;
    #pragma unroll
    for (int kk = 0; kk < 4; kk++)
        if (c[kk]) atomicAdd(&cnt[kk], c[kk]);
    __syncthreads();
    if (threadIdx.x < 4)
        g_blockhist[threadIdx.x * HB + blockIdx.x] = cnt[threadIdx.x];
}

// ---- sort pass 2: segmented scan -> per-block offsets + bucket starts ------
__global__ void scan_kernel(int n_rows)
{
    __shared__ int sh[4 * HB];
    int t = threadIdx.x;            // 0..1023, t = k*256 + b
    int orig = g_blockhist[t];
    sh[t] = orig;
    __syncthreads();
    for (int s = 1; s < HB; s <<= 1) {
        int add = ((t & (HB - 1)) >= s) ? sh[t - s] : 0;
        __syncthreads();
        sh[t] += add;
        __syncthreads();
    }
    int k = t >> 8;
    int kbase = 0;
    for (int kk = 0; kk < k; kk++) kbase += sh[kk * HB + HB - 1];
    g_blockoff[t] = kbase + (sh[t] - orig);
    if ((t & (HB - 1)) == 0) g_bucket_start[k] = kbase;
    if (t == 0) g_bucket_start[4] = n_rows;
}

// ---- sort pass 3: scatter row indices into buckets -------------------------
__global__ __launch_bounds__(256) void scatter_kernel(const int* __restrict__ kern_idx,
                                                      int n_rows)
{
    __shared__ int scur[4];
    if (threadIdx.x < 4)
        scur[threadIdx.x] = g_blockoff[threadIdx.x * HB + blockIdx.x];
    __syncthreads();
    int chunk = (n_rows + HB - 1) / HB;
    int i0 = blockIdx.x * chunk;
    int i1 = min(i0 + chunk, n_rows);
    int iters = (i1 > i0) ? ((i1 - i0 + 255) >> 8) : 0;
    int lane = threadIdx.x & 31;
    for (int it = 0; it < iters; it++) {
        int i = i0 + it * 256 + threadIdx.x;
        int k = (i < i1) ? kern_idx[i] : -1;
        #pragma unroll
        for (int kk = 0; kk < 4; kk++) {
            unsigned mask = __ballot_sync(0xFFFFFFFFu, k == kk);
            if (k == kk) {
                int leader = __ffs(mask) - 1;
                int base = 0;
                if (lane == leader) base = atomicAdd(&scur[kk], __popc(mask));
                base = __shfl_sync(mask, base, leader);
                int pos = base + __popc(mask & ((1u << lane) - 1));
                g_perm[pos] = i;
            }
        }
    }
}

// ---- conv: warp-per-ROW-PAIR, CHANNEL-SPLIT warps (32 weight regs) ---------
// Warp group = (k, chalf). Lane owns ONE channel c = chalf*32 + lane.
// Per iteration (2 rows): 1 LDGSTS (8B/lane), 16 broadcast LDS.128,
// 32 FFMA2 in 4 independent chains, 2 RED.32 (128B contiguous per warp).
// 32 weight regs -> ~70 total -> 6 warps/SMSP.
__global__ __launch_bounds__(128, 6) void conv_scatter(
    const float* __restrict__ feat,
    const float* __restrict__ weight,
    const int*   __restrict__ out_idx,
    float*       __restrict__ out)
{
    __shared__ ulonglong2 ring[4][4][16];   // [warp][stage][2 rows x 8] = 4KB
    int lane   = threadIdx.x & 31;
    int wlocal = threadIdx.x >> 5;
    int gw     = (blockIdx.x * blockDim.x + threadIdx.x) >> 5;
    int k      = gw & 3;
    int chalf  = (gw >> 2) & 1;
    int wslot  = gw >> 3;
    int nwb    = (gridDim.x * blockDim.x) >> 8;   // warps per (k,chalf) group

    // j-pair packed weights for the lane's single channel
    int c = chalf * 32 + lane;
    unsigned long long w[16];
    #pragma unroll
    for (int u = 0; u < 16; u++)
        w[u] = packpair(weight[(size_t)(k * 32 + 2 * u) * COUT + c],
                        weight[(size_t)(k * 32 + 2 * u + 1) * COUT + c]);

    int start = g_bucket_start[k];
    int end   = g_bucket_start[k + 1];
    if (start >= end) return;

    int p0 = start + wslot;
    int step = 2 * nwb;                       // row pair per iteration

    // index queue: ii[2t], ii[2t+1] = rows of iteration m+t (t=0..3), clamped
    int ii[8];
    #pragma unroll
    for (int j = 0; j < 8; j++) {
        int pc = p0 + j * nwb;
        pc = pc < end ? pc : end - 1;
        ii[j] = g_perm[pc];
    }
    int oq[4];
    oq[0] = out_idx[ii[0]]; oq[1] = out_idx[ii[1]];
    oq[2] = out_idx[ii[2]]; oq[3] = out_idx[ii[3]];

    unsigned sbase = (unsigned)__cvta_generic_to_shared(&ring[wlocal][0][0]);
    int half = lane >> 4;                     // 0: row a, 1: row b
    int hoff = (lane & 15) * 2;               // float offset within row

    // prologue: fill stages 0..2 (iterations 0,1,2)
    #pragma unroll
    for (int s = 0; s < 3; s++) {
        const float* g = feat + (size_t)ii[2 * s + half] * CIN + hoff;
        asm volatile("cp.async.ca.shared.global [%0], [%1], 8;"
                     :: "r"(sbase + s * 256 + lane * 8), "l"(g));
        asm volatile("cp.async.commit_group;");
    }

    int m = 0;
    for (int p = p0; p < end; p += step, m++) {
        // prefetch perm rows of iteration m+4
        int pa = p + 8 * nwb; pa = pa < end ? pa : end - 1;
        int pb = p + 9 * nwb; pb = pb < end ? pb : end - 1;
        int ia_new = g_perm[pa];
        int ib_new = g_perm[pb];
        // out rows of iteration m+2
        int oa_new = out_idx[ii[4]];
        int ob_new = out_idx[ii[5]];

        // fill stage for iteration m+3 (rows ii[6], ii[7])
        {
            int s = (m + 3) & 3;
            const float* g = feat + (size_t)ii[6 + half] * CIN + hoff;
            asm volatile("cp.async.ca.shared.global [%0], [%1], 8;"
                         :: "r"(sbase + s * 256 + lane * 8), "l"(g));
            asm volatile("cp.async.commit_group;");
        }
        asm volatile("cp.async.wait_group 3;");
        __syncwarp();

        const ulonglong2* q = ring[wlocal][m & 3];
        unsigned long long a0 = 0ull, a1 = 0ull;   // row a, 2 chains
        unsigned long long b0 = 0ull, b1 = 0ull;   // row b, 2 chains
        #pragma unroll
        for (int t = 0; t < 8; t++) {
            ulonglong2 qa = q[t];
            ulonglong2 qb = q[8 + t];
            a0 = ffma2(w[2 * t],     qa.x, a0);
            a1 = ffma2(w[2 * t + 1], qa.y, a1);
            b0 = ffma2(w[2 * t],     qb.x, b0);
            b1 = ffma2(w[2 * t + 1], qb.y, b1);
        }
        unsigned long long as, bs;
        asm("add.rn.f32x2 %0, %1, %2;" : "=l"(as) : "l"(a0), "l"(a1));
        asm("add.rn.f32x2 %0, %1, %2;" : "=l"(bs) : "l"(b0), "l"(b1));
        float x0, x1, y0, y1;
        unpack2(as, x0, x1);
        unpack2(bs, y0, y1);
        atomicAdd(out + (size_t)oq[0] * COUT + c, x0 + x1);  // warp: 128B contiguous
        if (p + nwb < end)                                    // guard tail row
            atomicAdd(out + (size_t)oq[1] * COUT + c, y0 + y1);

        // rotate queues by one iteration (2 entries)
        ii[0] = ii[2]; ii[1] = ii[3]; ii[2] = ii[4]; ii[3] = ii[5];
        ii[4] = ii[6]; ii[5] = ii[7]; ii[6] = ia_new; ii[7] = ib_new;
        oq[0] = oq[2]; oq[1] = oq[3]; oq[2] = oa_new; oq[3] = ob_new;
    }
    asm volatile("cp.async.wait_group 0;");   // drain before exit
}

// ---- stats: per-channel sum / sumsq partials -------------------------------
__global__ __launch_bounds__(256) void stats_kernel(const float* __restrict__ out,
                                                    int n_out)
{
    __shared__ float sh[128];
    if (threadIdx.x < 128) sh[threadIdx.x] = 0.f;
    __syncthreads();

    int gid = blockIdx.x * blockDim.x + threadIdx.x;
    int c4 = threadIdx.x & 15;
    int row0 = gid >> 4;
    int rstride = (gridDim.x * blockDim.x) >> 4;
    const float4* o4 = reinterpret_cast<const float4*>(out);

    float4 s = make_float4(0.f, 0.f, 0.f, 0.f);
    float4 q = make_float4(0.f, 0.f, 0.f, 0.f);
    for (int r = row0; r < n_out; r += rstride) {
        float4 v = o4[(size_t)r * 16 + c4];
        s.x += v.x; s.y += v.y; s.z += v.z; s.w += v.w;
        q.x += v.x * v.x; q.y += v.y * v.y; q.z += v.z * v.z; q.w += v.w * v.w;
    }
    s.x += __shfl_down_sync(0xFFFFFFFFu, s.x, 16);
    s.y += __shfl_down_sync(0xFFFFFFFFu, s.y, 16);
    s.z += __shfl_down_sync(0xFFFFFFFFu, s.z, 16);
    s.w += __shfl_down_sync(0xFFFFFFFFu, s.w, 16);
    q.x += __shfl_down_sync(0xFFFFFFFFu, q.x, 16);
    q.y += __shfl_down_sync(0xFFFFFFFFu, q.y, 16);
    q.z += __shfl_down_sync(0xFFFFFFFFu, q.z, 16);
    q.w += __shfl_down_sync(0xFFFFFFFFu, q.w, 16);

    if ((threadIdx.x & 31) < 16) {
        atomicAdd(&sh[c4 * 4 + 0], s.x);
        atomicAdd(&sh[c4 * 4 + 1], s.y);
        atomicAdd(&sh[c4 * 4 + 2], s.z);
        atomicAdd(&sh[c4 * 4 + 3], s.w);
        atomicAdd(&sh[64 + c4 * 4 + 0], q.x);
        atomicAdd(&sh[64 + c4 * 4 + 1], q.y);
        atomicAdd(&sh[64 + c4 * 4 + 2], q.z);
        atomicAdd(&sh[64 + c4 * 4 + 3], q.w);
    }
    __syncthreads();
    if (threadIdx.x < 128)
        g_partials[blockIdx.x * 128 + threadIdx.x] = sh[threadIdx.x];
}

// ---- reduce partials (parallel over 128 stat slots) ------------------------
__global__ __launch_bounds__(256) void reduce_kernel()
{
    int s = blockIdx.x;                 // 0..127
    float acc = 0.f;
    for (int b = threadIdx.x; b < STATS_BLOCKS; b += 256)
        acc += g_partials[b * 128 + s];
    __shared__ float sh[256];
    sh[threadIdx.x] = acc;
    __syncthreads();
    for (int st = 128; st > 0; st >>= 1) {
        if (threadIdx.x < st) sh[threadIdx.x] += sh[threadIdx.x + st];
        __syncthreads();
    }
    if (threadIdx.x == 0) g_tot[s] = sh[0];
}

// ---- coef: per-channel A,B -------------------------------------------------
__global__ void coef2_kernel(const float* __restrict__ gamma,
                             const float* __restrict__ beta,
                             int n_out)
{
    int t = threadIdx.x;   // 0..63
    float inv_n = 1.0f / (float)n_out;
    float mean = g_tot[t] * inv_n;
    float var  = g_tot[64 + t] * inv_n - mean * mean;
    float A = gamma[t] * rsqrtf(var + EPS);
    g_coef[t] = A;
    g_coef[64 + t] = beta[t] - mean * A;
}

// ---- norm + leaky relu (in place, at DRAM roofline) ------------------------
__global__ __launch_bounds__(256) void norm_kernel(float* __restrict__ out, int n_out)
{
    int gid = blockIdx.x * blockDim.x + threadIdx.x;
    int c4 = threadIdx.x & 15;
    const float4* cf = reinterpret_cast<const float4*>(g_coef);
    float4 A = cf[c4];
    float4 B = cf[16 + c4];
    int row0 = gid >> 4;
    int rstride = (gridDim.x * blockDim.x) >> 4;
    float4* o4 = reinterpret_cast<float4*>(out);
    for (int r = row0; r < n_out; r += rstride) {
        size_t idx = (size_t)r * 16 + c4;
        float4 v = o4[idx];
        float4 y;
        y.x = fmaf(v.x, A.x, B.x);
        y.y = fmaf(v.y, A.y, B.y);
        y.z = fmaf(v.z, A.z, B.z);
        y.w = fmaf(v.w, A.w, B.w);
        y.x = fmaxf(y.x, LEAK * y.x);
        y.y = fmaxf(y.y, LEAK * y.y);
        y.z = fmaxf(y.z, LEAK * y.z);
        y.w = fmaxf(y.w, LEAK * y.w);
        o4[idx] = y;
    }
}

// ---- launch ----------------------------------------------------------------
extern "C" void kernel_launch(void* const* d_in, const int* in_sizes, int n_in,
                              void* d_out, int out_size)
{
    const float* feat    = (const float*)d_in[0];
    const float* weight  = (const float*)d_in[1];
    // d_in[2] = bias: cancelled exactly by BN mean subtraction
    const float* gamma   = (const float*)d_in[3];
    const float* beta    = (const float*)d_in[4];
    const int*   out_idx = (const int*)d_in[5];
    const int*   kern_idx= (const int*)d_in[6];
    int n_rows = in_sizes[0] / CIN;
    int n_out  = out_size / COUT;
    float* out = (float*)d_out;

    cudaMemsetAsync(d_out, 0, (size_t)out_size * sizeof(float));
    hist_kernel<<<HB, 256>>>(kern_idx, n_rows);
    scan_kernel<<<1, 4 * HB>>>(n_rows);
    scatter_kernel<<<HB, 256>>>(kern_idx, n_rows);
    conv_scatter<<<CONV_BLOCKS, 128>>>(feat, weight, out_idx, out);  // 5th launch -> ncu slot
    stats_kernel<<<STATS_BLOCKS, 256>>>(out, n_out);
    reduce_kernel<<<128, 256>>>();
    coef2_kernel<<<1, 64>>>(gamma, beta, n_out);
    norm_kernel<<<1184, 256>>>(out, n_out);
}

// round 13
// speedup vs baseline: 1.4445x; 1.2780x over previous
#include <cuda_runtime.h>
#include <cstdint>

#define CIN   32
#define COUT  64
#define EPS   1e-4f
#define LEAK  0.333f

#define HB           256
#define N_MAX        1600000
#define CONV_BLOCKS  592           // 148 SMs * 4 blocks of 128
#define STATS_BLOCKS 1184

__device__ int   g_blockhist[4 * HB];
__device__ int   g_blockoff[4 * HB];
__device__ int   g_bucket_start[5];
__device__ int   g_perm[N_MAX];
__device__ float g_partials[STATS_BLOCKS * 128];
__device__ float g_tot[128];
__device__ float g_coef[128];

// ---- packed f32x2 helpers (sm_103a) ---------------------------------------
__device__ __forceinline__ unsigned long long packpair(float lo, float hi) {
    unsigned long long r;
    asm("mov.b64 %0, {%1, %2};" : "=l"(r) : "f"(lo), "f"(hi));
    return r;
}
__device__ __forceinline__ unsigned long long ffma2(unsigned long long a,
                                                    unsigned long long b,
                                                    unsigned long long c) {
    unsigned long long d;
    asm("fma.rn.f32x2 %0, %1, %2, %3;" : "=l"(d) : "l"(a), "l"(b), "l"(c));
    return d;
}
__device__ __forceinline__ void unpack2(unsigned long long v, float& lo, float& hi) {
    asm("mov.b64 {%0, %1}, %2;" : "=f"(lo), "=f"(hi) : "l"(v));
}

// ---- sort pass 1: per-block histogram of kern_idx --------------------------
__global__ __launch_bounds__(256) void hist_kernel(const int* __restrict__ kern_idx,
                                                   int n_rows)
{
    __shared__ int cnt[4];
    if (threadIdx.x < 4) cnt[threadIdx.x] = 0;
    __syncthreads();
    int chunk = (n_rows + HB - 1) / HB;
    int i0 = blockIdx.x * chunk;
    int i1 = min(i0 + chunk, n_rows);
    int c[4] = {0, 0, 0, 0};
    for (int i = i0 + threadIdx.x; i < i1; i += 256) c[kern_idx[i]]++;
    #pragma unroll
    for (int kk = 0; kk < 4; kk++)
        if (c[kk]) atomicAdd(&cnt[kk], c[kk]);
    __syncthreads();
    if (threadIdx.x < 4)
        g_blockhist[threadIdx.x * HB + blockIdx.x] = cnt[threadIdx.x];
}

// ---- sort pass 2: segmented scan -> per-block offsets + bucket starts ------
__global__ void scan_kernel(int n_rows)
{
    __shared__ int sh[4 * HB];
    int t = threadIdx.x;            // 0..1023, t = k*256 + b
    int orig = g_blockhist[t];
    sh[t] = orig;
    __syncthreads();
    for (int s = 1; s < HB; s <<= 1) {
        int add = ((t & (HB - 1)) >= s) ? sh[t - s] : 0;
        __syncthreads();
        sh[t] += add;
        __syncthreads();
    }
    int k = t >> 8;
    int kbase = 0;
    for (int kk = 0; kk < k; kk++) kbase += sh[kk * HB + HB - 1];
    g_blockoff[t] = kbase + (sh[t] - orig);
    if ((t & (HB - 1)) == 0) g_bucket_start[k] = kbase;
    if (t == 0) g_bucket_start[4] = n_rows;
}

// ---- sort pass 3: scatter row indices into buckets -------------------------
__global__ __launch_bounds__(256) void scatter_kernel(const int* __restrict__ kern_idx,
                                                      int n_rows)
{
    __shared__ int scur[4];
    if (threadIdx.x < 4)
        scur[threadIdx.x] = g_blockoff[threadIdx.x * HB + blockIdx.x];
    __syncthreads();
    int chunk = (n_rows + HB - 1) / HB;
    int i0 = blockIdx.x * chunk;
    int i1 = min(i0 + chunk, n_rows);
    int iters = (i1 > i0) ? ((i1 - i0 + 255) >> 8) : 0;
    int lane = threadIdx.x & 31;
    for (int it = 0; it < iters; it++) {
        int i = i0 + it * 256 + threadIdx.x;
        int k = (i < i1) ? kern_idx[i] : -1;
        #pragma unroll
        for (int kk = 0; kk < 4; kk++) {
            unsigned mask = __ballot_sync(0xFFFFFFFFu, k == kk);
            if (k == kk) {
                int leader = __ffs(mask) - 1;
                int base = 0;
                if (lane == leader) base = atomicAdd(&scur[kk], __popc(mask));
                base = __shfl_sync(mask, base, leader);
                int pos = base + __popc(mask & ((1u << lane) - 1));
                g_perm[pos] = i;
            }
        }
    }
}

// ---- conv: warp-per-4-ROWS, sequential pairs, smem row-index side ring -----
// lane l owns channels {2l,2l+1}. Per iteration (4 rows): 4 perm LDG (queued),
// 1 LDGSTS (16B/lane, 4 rows), 4 STS row-idx, 4 out_idx LDG (issued at compute
// start, consumed ~500 cyc later), 32 broadcast LDS.128, 128 FFMA2 in 4+4
// sequential-pair chains (acc regs reused), 4 RED.64. One wait per 4 rows.
__global__ __launch_bounds__(128, 4) void conv_scatter(
    const float* __restrict__ feat,
    const float* __restrict__ weight,
    const int*   __restrict__ out_idx,
    float*       __restrict__ out)
{
    __shared__ ulonglong2 ring[4][4][32];   // [warp][stage][4 rows x 8] = 8KB
    __shared__ int rq[4][4][4];             // row indices per [warp][stage][slot]
    int lane   = threadIdx.x & 31;
    int wlocal = threadIdx.x >> 5;
    int gw     = (blockIdx.x * blockDim.x + threadIdx.x) >> 5;
    int k      = gw & 3;
    int wslot  = gw >> 2;
    int nwb    = (gridDim.x * blockDim.x) >> 7;   // warps per bucket

    // j-pair packed weights for lane's two channels (64 regs)
    int c0 = 2 * lane;
    unsigned long long w0[16], w1[16];
    #pragma unroll
    for (int u = 0; u < 16; u++) {
        const float* r0p = weight + (size_t)(k * 32 + 2 * u) * COUT;
        const float* r1p = weight + (size_t)(k * 32 + 2 * u + 1) * COUT;
        w0[u] = packpair(r0p[c0],     r1p[c0]);
        w1[u] = packpair(r0p[c0 + 1], r1p[c0 + 1]);
    }

    int start = g_bucket_start[k];
    int end   = g_bucket_start[k + 1];
    if (start >= end) return;

    int p0 = start + wslot;

    unsigned sbase = (unsigned)__cvta_generic_to_shared(&ring[wlocal][0][0]);
    int rsel = lane >> 3;                      // which of 4 rows this lane fills
    int foff = (lane & 7) * 4;                 // float offset within row

    // prologue: fill stages 0..2 (iterations 0,1,2) + their rq slots
    #pragma unroll
    for (int s = 0; s < 3; s++) {
        int r0, r1, r2, r3;
        {
            int pc;
            pc = p0 + (4 * s + 0) * nwb; pc = pc < end ? pc : end - 1; r0 = g_perm[pc];
            pc = p0 + (4 * s + 1) * nwb; pc = pc < end ? pc : end - 1; r1 = g_perm[pc];
            pc = p0 + (4 * s + 2) * nwb; pc = pc < end ? pc : end - 1; r2 = g_perm[pc];
            pc = p0 + (4 * s + 3) * nwb; pc = pc < end ? pc : end - 1; r3 = g_perm[pc];
        }
        if (lane < 4)
            rq[wlocal][s][lane] = lane == 0 ? r0 : lane == 1 ? r1 : lane == 2 ? r2 : r3;
        int row = rsel == 0 ? r0 : rsel == 1 ? r1 : rsel == 2 ? r2 : r3;
        const float* g = feat + (size_t)row * CIN + foff;
        asm volatile("cp.async.ca.shared.global [%0], [%1], 16;"
                     :: "r"(sbase + s * 512 + lane * 16), "l"(g));
        asm volatile("cp.async.commit_group;");
    }
    // ii[0..3] = rows of iteration 3 (stage fill happens at m=0)
    int ii[8];
    #pragma unroll
    for (int j = 0; j < 4; j++) {
        int pc = p0 + (12 + j) * nwb;
        pc = pc < end ? pc : end - 1;
        ii[j] = g_perm[pc];
    }
    __syncwarp();

    int m = 0;
    for (int p = p0; p < end; p += 4 * nwb, m++) {
        // load rows of iteration m+4 (used next iteration for fill)
        {
            int pc;
            pc = p + 16 * nwb; pc = pc < end ? pc : end - 1; ii[4] = g_perm[pc];
            pc = p + 17 * nwb; pc = pc < end ? pc : end - 1; ii[5] = g_perm[pc];
            pc = p + 18 * nwb; pc = pc < end ? pc : end - 1; ii[6] = g_perm[pc];
            pc = p + 19 * nwb; pc = pc < end ? pc : end - 1; ii[7] = g_perm[pc];
        }
        // fill stage m+3 using ii[0..3] (loaded last iteration -> no LDG stall)
        {
            int sf = (m + 3) & 3;
            if (lane < 4)
                rq[wlocal][sf][lane] = lane == 0 ? ii[0] : lane == 1 ? ii[1]
                                     : lane == 2 ? ii[2] : ii[3];
            int row = rsel == 0 ? ii[0] : rsel == 1 ? ii[1] : rsel == 2 ? ii[2] : ii[3];
            const float* g = feat + (size_t)row * CIN + foff;
            asm volatile("cp.async.ca.shared.global [%0], [%1], 16;"
                         :: "r"(sbase + sf * 512 + lane * 16), "l"(g));
            asm volatile("cp.async.commit_group;");
        }
        asm volatile("cp.async.wait_group 3;");
        __syncwarp();

        // out rows for THIS iteration: uniform LDS from rq (written 3 iters
        // ago) + uniform LDG; results needed only at the REDs ~500 cyc later.
        const int* rqs = rq[wlocal][m & 3];
        int o0 = out_idx[rqs[0]];
        int o1 = out_idx[rqs[1]];
        int o2 = out_idx[rqs[2]];
        int o3 = out_idx[rqs[3]];

        const ulonglong2* q = ring[wlocal][m & 3];
        float x0, x1, y0, y1;

        // ---- pair A: rows 0,1 (4 chains, acc reused afterwards) ----
        {
            unsigned long long A0 = 0, B0 = 0, A1 = 0, B1 = 0;
            #pragma unroll
            for (int t = 0; t < 8; t++) {
                ulonglong2 qa = q[t];
                ulonglong2 qb = q[8 + t];
                A0 = ffma2(w0[2 * t],     qa.x, A0);
                B0 = ffma2(w1[2 * t],     qa.x, B0);
                A1 = ffma2(w0[2 * t],     qb.x, A1);
                B1 = ffma2(w1[2 * t],     qb.x, B1);
                A0 = ffma2(w0[2 * t + 1], qa.y, A0);
                B0 = ffma2(w1[2 * t + 1], qa.y, B0);
                A1 = ffma2(w0[2 * t + 1], qb.y, A1);
                B1 = ffma2(w1[2 * t + 1], qb.y, B1);
            }
            unsigned long long as, bs;
            asm("add.rn.f32x2 %0, %1, %2;" : "=l"(as) : "l"(A0), "l"(A1));
            // as now holds row0 ch-pair? keep rows separate:
            unpack2(A0, x0, x1); unpack2(B0, y0, y1);
            atomicAdd(reinterpret_cast<float2*>(out + (size_t)o0 * COUT + c0),
                      make_float2(x0 + x1, y0 + y1));
            if (p + 1 * nwb < end) {
                unpack2(A1, x0, x1); unpack2(B1, y0, y1);
                atomicAdd(reinterpret_cast<float2*>(out + (size_t)o1 * COUT + c0),
                          make_float2(x0 + x1, y0 + y1));
            }
            (void)as; (void)bs;
        }
        // ---- pair B: rows 2,3 ----
        {
            unsigned long long A2 = 0, B2 = 0, A3 = 0, B3 = 0;
            #pragma unroll
            for (int t = 0; t < 8; t++) {
                ulonglong2 qc = q[16 + t];
                ulonglong2 qd = q[24 + t];
                A2 = ffma2(w0[2 * t],     qc.x, A2);
                B2 = ffma2(w1[2 * t],     qc.x, B2);
                A3 = ffma2(w0[2 * t],     qd.x, A3);
                B3 = ffma2(w1[2 * t],     qd.x, B3);
                A2 = ffma2(w0[2 * t + 1], qc.y, A2);
                B2 = ffma2(w1[2 * t + 1], qc.y, B2);
                A3 = ffma2(w0[2 * t + 1], qd.y, A3);
                B3 = ffma2(w1[2 * t + 1], qd.y, B3);
            }
            if (p + 2 * nwb < end) {
                unpack2(A2, x0, x1); unpack2(B2, y0, y1);
                atomicAdd(reinterpret_cast<float2*>(out + (size_t)o2 * COUT + c0),
                          make_float2(x0 + x1, y0 + y1));
            }
            if (p + 3 * nwb < end) {
                unpack2(A3, x0, x1); unpack2(B3, y0, y1);
                atomicAdd(reinterpret_cast<float2*>(out + (size_t)o3 * COUT + c0),
                          make_float2(x0 + x1, y0 + y1));
            }
        }

        // rotate ii (one generation)
        ii[0] = ii[4]; ii[1] = ii[5]; ii[2] = ii[6]; ii[3] = ii[7];
    }
    asm volatile("cp.async.wait_group 0;");   // drain before exit
}

// ---- stats: per-channel sum / sumsq partials -------------------------------
__global__ __launch_bounds__(256) void stats_kernel(const float* __restrict__ out,
                                                    int n_out)
{
    __shared__ float sh[128];
    if (threadIdx.x < 128) sh[threadIdx.x] = 0.f;
    __syncthreads();

    int gid = blockIdx.x * blockDim.x + threadIdx.x;
    int c4 = threadIdx.x & 15;
    int row0 = gid >> 4;
    int rstride = (gridDim.x * blockDim.x) >> 4;
    const float4* o4 = reinterpret_cast<const float4*>(out);

    float4 s = make_float4(0.f, 0.f, 0.f, 0.f);
    float4 q = make_float4(0.f, 0.f, 0.f, 0.f);
    for (int r = row0; r < n_out; r += rstride) {
        float4 v = o4[(size_t)r * 16 + c4];
        s.x += v.x; s.y += v.y; s.z += v.z; s.w += v.w;
        q.x += v.x * v.x; q.y += v.y * v.y; q.z += v.z * v.z; q.w += v.w * v.w;
    }
    s.x += __shfl_down_sync(0xFFFFFFFFu, s.x, 16);
    s.y += __shfl_down_sync(0xFFFFFFFFu, s.y, 16);
    s.z += __shfl_down_sync(0xFFFFFFFFu, s.z, 16);
    s.w += __shfl_down_sync(0xFFFFFFFFu, s.w, 16);
    q.x += __shfl_down_sync(0xFFFFFFFFu, q.x, 16);
    q.y += __shfl_down_sync(0xFFFFFFFFu, q.y, 16);
    q.z += __shfl_down_sync(0xFFFFFFFFu, q.z, 16);
    q.w += __shfl_down_sync(0xFFFFFFFFu, q.w, 16);

    if ((threadIdx.x & 31) < 16) {
        atomicAdd(&sh[c4 * 4 + 0], s.x);
        atomicAdd(&sh[c4 * 4 + 1], s.y);
        atomicAdd(&sh[c4 * 4 + 2], s.z);
        atomicAdd(&sh[c4 * 4 + 3], s.w);
        atomicAdd(&sh[64 + c4 * 4 + 0], q.x);
        atomicAdd(&sh[64 + c4 * 4 + 1], q.y);
        atomicAdd(&sh[64 + c4 * 4 + 2], q.z);
        atomicAdd(&sh[64 + c4 * 4 + 3], q.w);
    }
    __syncthreads();
    if (threadIdx.x < 128)
        g_partials[blockIdx.x * 128 + threadIdx.x] = sh[threadIdx.x];
}

// ---- reduce partials (parallel over 128 stat slots) ------------------------
__global__ __launch_bounds__(256) void reduce_kernel()
{
    int s = blockIdx.x;                 // 0..127
    float acc = 0.f;
    for (int b = threadIdx.x; b < STATS_BLOCKS; b += 256)
        acc += g_partials[b * 128 + s];
    __shared__ float sh[256];
    sh[threadIdx.x] = acc;
    __syncthreads();
    for (int st = 128; st > 0; st >>= 1) {
        if (threadIdx.x < st) sh[threadIdx.x] += sh[threadIdx.x + st];
        __syncthreads();
    }
    if (threadIdx.x == 0) g_tot[s] = sh[0];
}

// ---- coef: per-channel A,B -------------------------------------------------
__global__ void coef2_kernel(const float* __restrict__ gamma,
                             const float* __restrict__ beta,
                             int n_out)
{
    int t = threadIdx.x;   // 0..63
    float inv_n = 1.0f / (float)n_out;
    float mean = g_tot[t] * inv_n;
    float var  = g_tot[64 + t] * inv_n - mean * mean;
    float A = gamma[t] * rsqrtf(var + EPS);
    g_coef[t] = A;
    g_coef[64 + t] = beta[t] - mean * A;
}

// ---- norm + leaky relu (in place, at DRAM roofline) ------------------------
__global__ __launch_bounds__(256) void norm_kernel(float* __restrict__ out, int n_out)
{
    int gid = blockIdx.x * blockDim.x + threadIdx.x;
    int c4 = threadIdx.x & 15;
    const float4* cf = reinterpret_cast<const float4*>(g_coef);
    float4 A = cf[c4];
    float4 B = cf[16 + c4];
    int row0 = gid >> 4;
    int rstride = (gridDim.x * blockDim.x) >> 4;
    float4* o4 = reinterpret_cast<float4*>(out);
    for (int r = row0; r < n_out; r += rstride) {
        size_t idx = (size_t)r * 16 + c4;
        float4 v = o4[idx];
        float4 y;
        y.x = fmaf(v.x, A.x, B.x);
        y.y = fmaf(v.y, A.y, B.y);
        y.z = fmaf(v.z, A.z, B.z);
        y.w = fmaf(v.w, A.w, B.w);
        y.x = fmaxf(y.x, LEAK * y.x);
        y.y = fmaxf(y.y, LEAK * y.y);
        y.z = fmaxf(y.z, LEAK * y.z);
        y.w = fmaxf(y.w, LEAK * y.w);
        o4[idx] = y;
    }
}

// ---- launch ----------------------------------------------------------------
extern "C" void kernel_launch(void* const* d_in, const int* in_sizes, int n_in,
                              void* d_out, int out_size)
{
    const float* feat    = (const float*)d_in[0];
    const float* weight  = (const float*)d_in[1];
    // d_in[2] = bias: cancelled exactly by BN mean subtraction
    const float* gamma   = (const float*)d_in[3];
    const float* beta    = (const float*)d_in[4];
    const int*   out_idx = (const int*)d_in[5];
    const int*   kern_idx= (const int*)d_in[6];
    int n_rows = in_sizes[0] / CIN;
    int n_out  = out_size / COUT;
    float* out = (float*)d_out;

    cudaMemsetAsync(d_out, 0, (size_t)out_size * sizeof(float));
    hist_kernel<<<HB, 256>>>(kern_idx, n_rows);
    scan_kernel<<<1, 4 * HB>>>(n_rows);
    scatter_kernel<<<HB, 256>>>(kern_idx, n_rows);
    conv_scatter<<<CONV_BLOCKS, 128>>>(feat, weight, out_idx, out);  // 5th launch -> ncu slot
    stats_kernel<<<STATS_BLOCKS, 256>>>(out, n_out);
    reduce_kernel<<<128, 256>>>();
    coef2_kernel<<<1, 64>>>(gamma, beta, n_out);
    norm_kernel<<<1184, 256>>>(out, n_out);
}

// round 14
// speedup vs baseline: 1.4553x; 1.0074x over previous
#include <cuda_runtime.h>
#include <cstdint>

#define CIN   32
#define COUT  64
#define EPS   1e-4f
#define LEAK  0.333f

#define HB           256
#define N_MAX        1600000
#define CONV_BLOCKS  592           // 148 SMs * 4 blocks of 128
#define STATS_BLOCKS 1184

__device__ int   g_blockhist[4 * HB];
__device__ int   g_blockoff[4 * HB];
__device__ int   g_bucket_start[5];
__device__ int   g_perm[N_MAX];
__device__ float g_partials[STATS_BLOCKS * 128];
__device__ float g_tot[128];
__device__ float g_coef[128];

// ---- packed f32x2 helpers (sm_103a) ---------------------------------------
__device__ __forceinline__ unsigned long long packpair(float lo, float hi) {
    unsigned long long r;
    asm("mov.b64 %0, {%1, %2};" : "=l"(r) : "f"(lo), "f"(hi));
    return r;
}
__device__ __forceinline__ unsigned long long ffma2(unsigned long long a,
                                                    unsigned long long b,
                                                    unsigned long long c) {
    unsigned long long d;
    asm("fma.rn.f32x2 %0, %1, %2, %3;" : "=l"(d) : "l"(a), "l"(b), "l"(c));
    return d;
}
__device__ __forceinline__ void unpack2(unsigned long long v, float& lo, float& hi) {
    asm("mov.b64 {%0, %1}, %2;" : "=f"(lo), "=f"(hi) : "l"(v));
}

// ---- sort pass 1: per-block histogram of kern_idx --------------------------
__global__ __launch_bounds__(256) void hist_kernel(const int* __restrict__ kern_idx,
                                                   int n_rows)
{
    __shared__ int cnt[4];
    if (threadIdx.x < 4) cnt[threadIdx.x] = 0;
    __syncthreads();
    int chunk = (n_rows + HB - 1) / HB;
    int i0 = blockIdx.x * chunk;
    int i1 = min(i0 + chunk, n_rows);
    int c[4] = {0, 0, 0, 0};
    for (int i = i0 + threadIdx.x; i < i1; i += 256) c[kern_idx[i]]++;
    #pragma unroll
    for (int kk = 0; kk < 4; kk++)
        if (c[kk]) atomicAdd(&cnt[kk], c[kk]);
    __syncthreads();
    if (threadIdx.x < 4)
        g_blockhist[threadIdx.x * HB + blockIdx.x] = cnt[threadIdx.x];
}

// ---- sort pass 2: segmented scan -> per-block offsets + bucket starts ------
__global__ void scan_kernel(int n_rows)
{
    __shared__ int sh[4 * HB];
    int t = threadIdx.x;            // 0..1023, t = k*256 + b
    int orig = g_blockhist[t];
    sh[t] = orig;
    __syncthreads();
    for (int s = 1; s < HB; s <<= 1) {
        int add = ((t & (HB - 1)) >= s) ? sh[t - s] : 0;
        __syncthreads();
        sh[t] += add;
        __syncthreads();
    }
    int k = t >> 8;
    int kbase = 0;
    for (int kk = 0; kk < k; kk++) kbase += sh[kk * HB + HB - 1];
    g_blockoff[t] = kbase + (sh[t] - orig);
    if ((t & (HB - 1)) == 0) g_bucket_start[k] = kbase;
    if (t == 0) g_bucket_start[4] = n_rows;
}

// ---- sort pass 3: scatter row indices into buckets -------------------------
__global__ __launch_bounds__(256) void scatter_kernel(const int* __restrict__ kern_idx,
                                                      int n_rows)
{
    __shared__ int scur[4];
    if (threadIdx.x < 4)
        scur[threadIdx.x] = g_blockoff[threadIdx.x * HB + blockIdx.x];
    __syncthreads();
    int chunk = (n_rows + HB - 1) / HB;
    int i0 = blockIdx.x * chunk;
    int i1 = min(i0 + chunk, n_rows);
    int iters = (i1 > i0) ? ((i1 - i0 + 255) >> 8) : 0;
    int lane = threadIdx.x & 31;
    for (int it = 0; it < iters; it++) {
        int i = i0 + it * 256 + threadIdx.x;
        int k = (i < i1) ? kern_idx[i] : -1;
        #pragma unroll
        for (int kk = 0; kk < 4; kk++) {
            unsigned mask = __ballot_sync(0xFFFFFFFFu, k == kk);
            if (k == kk) {
                int leader = __ffs(mask) - 1;
                int base = 0;
                if (lane == leader) base = atomicAdd(&scur[kk], __popc(mask));
                base = __shfl_sync(mask, base, leader);
                int pos = base + __popc(mask & ((1u << lane) - 1));
                g_perm[pos] = i;
            }
        }
    }
}

// ---- conv: warp-per-4-ROWS, sequential pairs, smem row-index side ring -----
// lane l owns channels {2l,2l+1}. Per iteration (4 rows): 4 perm LDG (queued),
// 1 LDGSTS (16B/lane, 4 rows), 4 STS row-idx, 4 out_idx LDG (issued at compute
// start, consumed ~500 cyc later), 32 broadcast LDS.128, 128 FFMA2 in 4+4
// sequential-pair chains (acc regs reused), 4 RED.64. One wait per 4 rows.
__global__ __launch_bounds__(128, 4) void conv_scatter(
    const float* __restrict__ feat,
    const float* __restrict__ weight,
    const int*   __restrict__ out_idx,
    float*       __restrict__ out)
{
    __shared__ ulonglong2 ring[4][4][32];   // [warp][stage][4 rows x 8] = 8KB
    __shared__ int rq[4][4][4];             // row indices per [warp][stage][slot]
    int lane   = threadIdx.x & 31;
    int wlocal = threadIdx.x >> 5;
    int gw     = (blockIdx.x * blockDim.x + threadIdx.x) >> 5;
    int k      = gw & 3;
    int wslot  = gw >> 2;
    int nwb    = (gridDim.x * blockDim.x) >> 7;   // warps per bucket

    // j-pair packed weights for lane's two channels (64 regs)
    int c0 = 2 * lane;
    unsigned long long w0[16], w1[16];
    #pragma unroll
    for (int u = 0; u < 16; u++) {
        const float* r0p = weight + (size_t)(k * 32 + 2 * u) * COUT;
        const float* r1p = weight + (size_t)(k * 32 + 2 * u + 1) * COUT;
        w0[u] = packpair(r0p[c0],     r1p[c0]);
        w1[u] = packpair(r0p[c0 + 1], r1p[c0 + 1]);
    }

    int start = g_bucket_start[k];
    int end   = g_bucket_start[k + 1];
    if (start >= end) return;

    int p0 = start + wslot;

    unsigned sbase = (unsigned)__cvta_generic_to_shared(&ring[wlocal][0][0]);
    int rsel = lane >> 3;                      // which of 4 rows this lane fills
    int foff = (lane & 7) * 4;                 // float offset within row

    // prologue: fill stages 0..2 (iterations 0,1,2) + their rq slots
    #pragma unroll
    for (int s = 0; s < 3; s++) {
        int r0, r1, r2, r3;
        {
            int pc;
            pc = p0 + (4 * s + 0) * nwb; pc = pc < end ? pc : end - 1; r0 = g_perm[pc];
            pc = p0 + (4 * s + 1) * nwb; pc = pc < end ? pc : end - 1; r1 = g_perm[pc];
            pc = p0 + (4 * s + 2) * nwb; pc = pc < end ? pc : end - 1; r2 = g_perm[pc];
            pc = p0 + (4 * s + 3) * nwb; pc = pc < end ? pc : end - 1; r3 = g_perm[pc];
        }
        if (lane < 4)
            rq[wlocal][s][lane] = lane == 0 ? r0 : lane == 1 ? r1 : lane == 2 ? r2 : r3;
        int row = rsel == 0 ? r0 : rsel == 1 ? r1 : rsel == 2 ? r2 : r3;
        const float* g = feat + (size_t)row * CIN + foff;
        asm volatile("cp.async.ca.shared.global [%0], [%1], 16;"
                     :: "r"(sbase + s * 512 + lane * 16), "l"(g));
        asm volatile("cp.async.commit_group;");
    }
    // ii[0..3] = rows of iteration 3 (stage fill happens at m=0)
    int ii[8];
    #pragma unroll
    for (int j = 0; j < 4; j++) {
        int pc = p0 + (12 + j) * nwb;
        pc = pc < end ? pc : end - 1;
        ii[j] = g_perm[pc];
    }
    __syncwarp();

    int m = 0;
    for (int p = p0; p < end; p += 4 * nwb, m++) {
        // load rows of iteration m+4 (used next iteration for fill)
        {
            int pc;
            pc = p + 16 * nwb; pc = pc < end ? pc : end - 1; ii[4] = g_perm[pc];
            pc = p + 17 * nwb; pc = pc < end ? pc : end - 1; ii[5] = g_perm[pc];
            pc = p + 18 * nwb; pc = pc < end ? pc : end - 1; ii[6] = g_perm[pc];
            pc = p + 19 * nwb; pc = pc < end ? pc : end - 1; ii[7] = g_perm[pc];
        }
        // fill stage m+3 using ii[0..3] (loaded last iteration -> no LDG stall)
        {
            int sf = (m + 3) & 3;
            if (lane < 4)
                rq[wlocal][sf][lane] = lane == 0 ? ii[0] : lane == 1 ? ii[1]
                                     : lane == 2 ? ii[2] : ii[3];
            int row = rsel == 0 ? ii[0] : rsel == 1 ? ii[1] : rsel == 2 ? ii[2] : ii[3];
            const float* g = feat + (size_t)row * CIN + foff;
            asm volatile("cp.async.ca.shared.global [%0], [%1], 16;"
                         :: "r"(sbase + sf * 512 + lane * 16), "l"(g));
            asm volatile("cp.async.commit_group;");
        }
        asm volatile("cp.async.wait_group 3;");
        __syncwarp();

        // out rows for THIS iteration: uniform LDS from rq (written 3 iters
        // ago) + uniform LDG; results needed only at the REDs ~500 cyc later.
        const int* rqs = rq[wlocal][m & 3];
        int o0 = out_idx[rqs[0]];
        int o1 = out_idx[rqs[1]];
        int o2 = out_idx[rqs[2]];
        int o3 = out_idx[rqs[3]];

        const ulonglong2* q = ring[wlocal][m & 3];
        float x0, x1, y0, y1;

        // ---- pair A: rows 0,1 (4 chains, acc reused afterwards) ----
        {
            unsigned long long A0 = 0, B0 = 0, A1 = 0, B1 = 0;
            #pragma unroll
            for (int t = 0; t < 8; t++) {
                ulonglong2 qa = q[t];
                ulonglong2 qb = q[8 + t];
                A0 = ffma2(w0[2 * t],     qa.x, A0);
                B0 = ffma2(w1[2 * t],     qa.x, B0);
                A1 = ffma2(w0[2 * t],     qb.x, A1);
                B1 = ffma2(w1[2 * t],     qb.x, B1);
                A0 = ffma2(w0[2 * t + 1], qa.y, A0);
                B0 = ffma2(w1[2 * t + 1], qa.y, B0);
                A1 = ffma2(w0[2 * t + 1], qb.y, A1);
                B1 = ffma2(w1[2 * t + 1], qb.y, B1);
            }
            unsigned long long as, bs;
            asm("add.rn.f32x2 %0, %1, %2;" : "=l"(as) : "l"(A0), "l"(A1));
            // as now holds row0 ch-pair? keep rows separate:
            unpack2(A0, x0, x1); unpack2(B0, y0, y1);
            atomicAdd(reinterpret_cast<float2*>(out + (size_t)o0 * COUT + c0),
                      make_float2(x0 + x1, y0 + y1));
            if (p + 1 * nwb < end) {
                unpack2(A1, x0, x1); unpack2(B1, y0, y1);
                atomicAdd(reinterpret_cast<float2*>(out + (size_t)o1 * COUT + c0),
                          make_float2(x0 + x1, y0 + y1));
            }
            (void)as; (void)bs;
        }
        // ---- pair B: rows 2,3 ----
        {
            unsigned long long A2 = 0, B2 = 0, A3 = 0, B3 = 0;
            #pragma unroll
            for (int t = 0; t < 8; t++) {
                ulonglong2 qc = q[16 + t];
                ulonglong2 qd = q[24 + t];
                A2 = ffma2(w0[2 * t],     qc.x, A2);
                B2 = ffma2(w1[2 * t],     qc.x, B2);
                A3 = ffma2(w0[2 * t],     qd.x, A3);
                B3 = ffma2(w1[2 * t],     qd.x, B3);
                A2 = ffma2(w0[2 * t + 1], qc.y, A2);
                B2 = ffma2(w1[2 * t + 1], qc.y, B2);
                A3 = ffma2(w0[2 * t + 1], qd.y, A3);
                B3 = ffma2(w1[2 * t + 1], qd.y, B3);
            }
            if (p + 2 * nwb < end) {
                unpack2(A2, x0, x1); unpack2(B2, y0, y1);
                atomicAdd(reinterpret_cast<float2*>(out + (size_t)o2 * COUT + c0),
                          make_float2(x0 + x1, y0 + y1));
            }
            if (p + 3 * nwb < end) {
                unpack2(A3, x0, x1); unpack2(B3, y0, y1);
                atomicAdd(reinterpret_cast<float2*>(out + (size_t)o3 * COUT + c0),
                          make_float2(x0 + x1, y0 + y1));
            }
        }

        // rotate ii (one generation)
        ii[0] = ii[4]; ii[1] = ii[5]; ii[2] = ii[6]; ii[3] = ii[7];
    }
    asm volatile("cp.async.wait_group 0;");   // drain before exit
}

// ---- stats: per-channel sum / sumsq partials -------------------------------
__global__ __launch_bounds__(256) void stats_kernel(const float* __restrict__ out,
                                                    int n_out)
{
    __shared__ float sh[128];
    if (threadIdx.x < 128) sh[threadIdx.x] = 0.f;
    __syncthreads();

    int gid = blockIdx.x * blockDim.x + threadIdx.x;
    int c4 = threadIdx.x & 15;
    int row0 = gid >> 4;
    int rstride = (gridDim.x * blockDim.x) >> 4;
    const float4* o4 = reinterpret_cast<const float4*>(out);

    float4 s = make_float4(0.f, 0.f, 0.f, 0.f);
    float4 q = make_float4(0.f, 0.f, 0.f, 0.f);
    for (int r = row0; r < n_out; r += rstride) {
        float4 v = o4[(size_t)r * 16 + c4];
        s.x += v.x; s.y += v.y; s.z += v.z; s.w += v.w;
        q.x += v.x * v.x; q.y += v.y * v.y; q.z += v.z * v.z; q.w += v.w * v.w;
    }
    s.x += __shfl_down_sync(0xFFFFFFFFu, s.x, 16);
    s.y += __shfl_down_sync(0xFFFFFFFFu, s.y, 16);
    s.z += __shfl_down_sync(0xFFFFFFFFu, s.z, 16);
    s.w += __shfl_down_sync(0xFFFFFFFFu, s.w, 16);
    q.x += __shfl_down_sync(0xFFFFFFFFu, q.x, 16);
    q.y += __shfl_down_sync(0xFFFFFFFFu, q.y, 16);
    q.z += __shfl_down_sync(0xFFFFFFFFu, q.z, 16);
    q.w += __shfl_down_sync(0xFFFFFFFFu, q.w, 16);

    if ((threadIdx.x & 31) < 16) {
        atomicAdd(&sh[c4 * 4 + 0], s.x);
        atomicAdd(&sh[c4 * 4 + 1], s.y);
        atomicAdd(&sh[c4 * 4 + 2], s.z);
        atomicAdd(&sh[c4 * 4 + 3], s.w);
        atomicAdd(&sh[64 + c4 * 4 + 0], q.x);
        atomicAdd(&sh[64 + c4 * 4 + 1], q.y);
        atomicAdd(&sh[64 + c4 * 4 + 2], q.z);
        atomicAdd(&sh[64 + c4 * 4 + 3], q.w);
    }
    __syncthreads();
    if (threadIdx.x < 128)
        g_partials[blockIdx.x * 128 + threadIdx.x] = sh[threadIdx.x];
}

// ---- reduce partials (parallel over 128 stat slots) ------------------------
__global__ __launch_bounds__(256) void reduce_kernel()
{
    int s = blockIdx.x;                 // 0..127
    float acc = 0.f;
    for (int b = threadIdx.x; b < STATS_BLOCKS; b += 256)
        acc += g_partials[b * 128 + s];
    __shared__ float sh[256];
    sh[threadIdx.x] = acc;
    __syncthreads();
    for (int st = 128; st > 0; st >>= 1) {
        if (threadIdx.x < st) sh[threadIdx.x] += sh[threadIdx.x + st];
        __syncthreads();
    }
    if (threadIdx.x == 0) g_tot[s] = sh[0];
}

// ---- coef: per-channel A,B -------------------------------------------------
__global__ void coef2_kernel(const float* __restrict__ gamma,
                             const float* __restrict__ beta,
                             int n_out)
{
    int t = threadIdx.x;   // 0..63
    float inv_n = 1.0f / (float)n_out;
    float mean = g_tot[t] * inv_n;
    float var  = g_tot[64 + t] * inv_n - mean * mean;
    float A = gamma[t] * rsqrtf(var + EPS);
    g_coef[t] = A;
    g_coef[64 + t] = beta[t] - mean * A;
}

// ---- norm + leaky relu (in place, at DRAM roofline) ------------------------
__global__ __launch_bounds__(256) void norm_kernel(float* __restrict__ out, int n_out)
{
    int gid = blockIdx.x * blockDim.x + threadIdx.x;
    int c4 = threadIdx.x & 15;
    const float4* cf = reinterpret_cast<const float4*>(g_coef);
    float4 A = cf[c4];
    float4 B = cf[16 + c4];
    int row0 = gid >> 4;
    int rstride = (gridDim.x * blockDim.x) >> 4;
    float4* o4 = reinterpret_cast<float4*>(out);
    for (int r = row0; r < n_out; r += rstride) {
        size_t idx = (size_t)r * 16 + c4;
        float4 v = o4[idx];
        float4 y;
        y.x = fmaf(v.x, A.x, B.x);
        y.y = fmaf(v.y, A.y, B.y);
        y.z = fmaf(v.z, A.z, B.z);
        y.w = fmaf(v.w, A.w, B.w);
        y.x = fmaxf(y.x, LEAK * y.x);
        y.y = fmaxf(y.y, LEAK * y.y);
        y.z = fmaxf(y.z, LEAK * y.z);
        y.w = fmaxf(y.w, LEAK * y.w);
        o4[idx] = y;
    }
}

// ---- launch ----------------------------------------------------------------
extern "C" void kernel_launch(void* const* d_in, const int* in_sizes, int n_in,
                              void* d_out, int out_size)
{
    const float* feat    = (const float*)d_in[0];
    const float* weight  = (const float*)d_in[1];
    // d_in[2] = bias: cancelled exactly by BN mean subtraction
    const float* gamma   = (const float*)d_in[3];
    const float* beta    = (const float*)d_in[4];
    const int*   out_idx = (const int*)d_in[5];
    const int*   kern_idx= (const int*)d_in[6];
    int n_rows = in_sizes[0] / CIN;
    int n_out  = out_size / COUT;
    float* out = (float*)d_out;

    cudaMemsetAsync(d_out, 0, (size_t)out_size * sizeof(float));
    hist_kernel<<<HB, 256>>>(kern_idx, n_rows);
    scan_kernel<<<1, 4 * HB>>>(n_rows);
    scatter_kernel<<<HB, 256>>>(kern_idx, n_rows);
    conv_scatter<<<CONV_BLOCKS, 128>>>(feat, weight, out_idx, out);  // 5th launch -> ncu slot
    stats_kernel<<<STATS_BLOCKS, 256>>>(out, n_out);
    reduce_kernel<<<128, 256>>>();
    coef2_kernel<<<1, 64>>>(gamma, beta, n_out);
    norm_kernel<<<1184, 256>>>(out, n_out);
}

// round 16
// speedup vs baseline: 1.4572x; 1.0013x over previous
#include <cuda_runtime.h>
#include <cuda_bf16.h>
#include <cstdint>

#define CIN 32
#define COUT 64
#define EPS 1e-4f
#define LEAK 0.333f
#define HB 256
#define N_MAX 1600000
#define CONV_BLOCKS 592            // multiple of 4; k = blockIdx.x & 3
#define STATS_BLOCKS 1184

__device__ int   g_blockhist[4 * HB];
__device__ int   g_blockoff[4 * HB];
__device__ int   g_bucket_start[5];
__device__ int   g_perm[N_MAX];
__device__ float g_partials[STATS_BLOCKS * 128];
__device__ float g_tot[128];
__device__ float g_coef[128];

// pack two f32 -> bf16x2, low16 = bf16(lo), high16 = bf16(hi)
__device__ __forceinline__ unsigned bf2(float lo, float hi) {
    unsigned r;
    asm("cvt.rn.bf16x2.f32 %0, %1, %2;" : "=r"(r) : "f"(hi), "f"(lo));
    return r;
}
// split a float2 into hi bf16x2 and residual-lo bf16x2
__device__ __forceinline__ void split2(float2 v, unsigned& hi, unsigned& lo) {
    hi = bf2(v.x, v.y);
    float hx = __uint_as_float(hi << 16);
    float hy = __uint_as_float(hi & 0xFFFF0000u);
    lo = bf2(v.x - hx, v.y - hy);
}
__device__ __forceinline__ void mma16816(float& c0, float& c1, float& c2, float& c3,
                                         unsigned a0, unsigned a1, unsigned a2, unsigned a3,
                                         unsigned b0, unsigned b1) {
    asm volatile("mma.sync.aligned.m16n8k16.row.col.f32.bf16.bf16.f32 "
                 "{%0,%1,%2,%3}, {%4,%5,%6,%7}, {%8,%9}, {%0,%1,%2,%3};"
                 : "+f"(c0), "+f"(c1), "+f"(c2), "+f"(c3)
                 : "r"(a0), "r"(a1), "r"(a2), "r"(a3), "r"(b0), "r"(b1));
}

// ---- sort pass 1: per-block histogram of kern_idx --------------------------
__global__ __launch_bounds__(256) void hist_kernel(const int* __restrict__ kern_idx, int n_rows)
{
    __shared__ int cnt[4];
    if (threadIdx.x < 4) cnt[threadIdx.x] = 0;
    __syncthreads();
    int chunk = (n_rows + HB - 1) / HB;
    int i0 = blockIdx.x * chunk, i1 = min(i0 + chunk, n_rows);
    int c[4] = {0, 0, 0, 0};
    for (int i = i0 + threadIdx.x; i < i1; i += 256) c[kern_idx[i]]++;
    #pragma unroll
    for (int kk = 0; kk < 4; kk++)
        if (c[kk]) atomicAdd(&cnt[kk], c[kk]);
    __syncthreads();
    if (threadIdx.x < 4) g_blockhist[threadIdx.x * HB + blockIdx.x] = cnt[threadIdx.x];
}

// ---- sort pass 2: segmented scan -> per-block offsets + bucket starts ------
__global__ void scan_kernel(int n_rows)
{
    __shared__ int sh[4 * HB];
    int t = threadIdx.x;
    int orig = g_blockhist[t];
    sh[t] = orig;
    __syncthreads();
    for (int s = 1; s < HB; s <<= 1) {
        int add = ((t & (HB - 1)) >= s) ? sh[t - s] : 0;
        __syncthreads();
        sh[t] += add;
        __syncthreads();
    }
    int k = t >> 8, kbase = 0;
    for (int kk = 0; kk < k; kk++) kbase += sh[kk * HB + HB - 1];
    g_blockoff[t] = kbase + (sh[t] - orig);
    if ((t & (HB - 1)) == 0) g_bucket_start[k] = kbase;
    if (t == 0) g_bucket_start[4] = n_rows;
}

// ---- sort pass 3: scatter row indices into buckets -------------------------
__global__ __launch_bounds__(256) void scatter_kernel(const int* __restrict__ kern_idx, int n_rows)
{
    __shared__ int scur[4];
    if (threadIdx.x < 4) scur[threadIdx.x] = g_blockoff[threadIdx.x * HB + blockIdx.x];
    __syncthreads();
    int chunk = (n_rows + HB - 1) / HB;
    int i0 = blockIdx.x * chunk, i1 = min(i0 + chunk, n_rows);
    int iters = (i1 > i0) ? ((i1 - i0 + 255) >> 8) : 0;
    int lane = threadIdx.x & 31;
    for (int it = 0; it < iters; it++) {
        int i = i0 + it * 256 + threadIdx.x;
        int k = (i < i1) ? kern_idx[i] : -1;
        #pragma unroll
        for (int kk = 0; kk < 4; kk++) {
            unsigned mask = __ballot_sync(0xFFFFFFFFu, k == kk);
            if (k == kk) {
                int leader = __ffs(mask) - 1, base = 0;
                if (lane == leader) base = atomicAdd(&scur[kk], __popc(mask));
                base = __shfl_sync(mask, base, leader);
                g_perm[base + __popc(mask & ((1u << lane) - 1))] = i;
            }
        }
    }
}

// ---- conv via HMMA mma.sync (bf16 two-term split, K-stack 96) --------------
// Block owns bucket k = blockIdx.x & 3. Warp processes 16 rows/iter:
// lane(gID,tig) gathers its A-fragment elements directly (8 LDG.64),
// converts to hi/lo bf16x2, then 8 n-slices x 6 HMMA + 2 predicated RED.64.
// B fragments precomputed once into smem (4 unique pairs per slice).
__global__ __launch_bounds__(256) void conv_mma(
    const float* __restrict__ feat,
    const float* __restrict__ weight,
    const int*   __restrict__ out_idx,
    float*       __restrict__ out)
{
    __shared__ unsigned long long Bs[8][4][32];  // [slice][bh0,bh1,bl0,bl1][lane]
    int t = threadIdx.x;
    int lane = t & 31;
    int gID = lane >> 2, tig = lane & 3;
    int k = blockIdx.x & 3;

    // ---- precompute B fragments (once) ----
    {
        int slice = t >> 5;
        int n = slice * 8 + gID;
        #pragma unroll
        for (int pid = 0; pid < 2; pid++) {        // j-base 0 / 16
            int jb = pid * 16 + 2 * tig;
            float w00 = weight[(size_t)(k * 32 + jb) * COUT + n];
            float w01 = weight[(size_t)(k * 32 + jb + 1) * COUT + n];
            float w08 = weight[(size_t)(k * 32 + jb + 8) * COUT + n];
            float w09 = weight[(size_t)(k * 32 + jb + 9) * COUT + n];
            unsigned h0, l0, h1, l1;
            split2(make_float2(w00, w01), h0, l0);
            split2(make_float2(w08, w09), h1, l1);
            Bs[slice][pid][lane]     = ((unsigned long long)h1 << 32) | h0;
            Bs[slice][2 + pid][lane] = ((unsigned long long)l1 << 32) | l0;
        }
    }
    __syncthreads();

    int start = g_bucket_start[k], end = g_bucket_start[k + 1];
    int wid = t >> 5;
    int wslot = (blockIdx.x >> 2) * 8 + wid;
    int nwb = ((int)gridDim.x >> 2) * 8;          // warps per bucket

    for (int p = start + wslot * 16; p < end; p += nwb * 16) {
        int p0 = p + gID, p1 = p + 8 + gID;
        int pc0 = p0 < end ? p0 : end - 1;
        int pc1 = p1 < end ? p1 : end - 1;
        int i0 = g_perm[pc0], i1 = g_perm[pc1];
        int o0 = (p0 < end) ? out_idx[i0] : -1;
        int o1 = (p1 < end) ? out_idx[i1] : -1;
        const float2* f0 = (const float2*)(feat + (size_t)i0 * CIN);
        const float2* f1 = (const float2*)(feat + (size_t)i1 * CIN);

        // A fragments: rows gID (ah/al[0]) and gID+8 (ah/al[1]);
        // q-th pair = features j in {2tig, 2tig+1} + 8q
        unsigned ah[2][4], al[2][4];
        #pragma unroll
        for (int q = 0; q < 4; q++) split2(f0[tig + 4 * q], ah[0][q], al[0][q]);
        #pragma unroll
        for (int q = 0; q < 4; q++) split2(f1[tig + 4 * q], ah[1][q], al[1][q]);

        #pragma unroll
        for (int sl = 0; sl < 8; sl++) {
            unsigned long long q0 = Bs[sl][0][lane];   // b_hi j0-15
            unsigned long long q1 = Bs[sl][1][lane];   // b_hi j16-31
            unsigned long long q2 = Bs[sl][2][lane];   // b_lo j0-15
            unsigned long long q3 = Bs[sl][3][lane];   // b_lo j16-31
            float c0 = 0.f, c1 = 0.f, c2 = 0.f, c3 = 0.f;
            // a_hi * b_hi
            mma16816(c0, c1, c2, c3, ah[0][0], ah[1][0], ah[0][1], ah[1][1],
                     (unsigned)q0, (unsigned)(q0 >> 32));
            mma16816(c0, c1, c2, c3, ah[0][2], ah[1][2], ah[0][3], ah[1][3],
                     (unsigned)q1, (unsigned)(q1 >> 32));
            // a_lo * b_hi
            mma16816(c0, c1, c2, c3, al[0][0], al[1][0], al[0][1], al[1][1],
                     (unsigned)q0, (unsigned)(q0 >> 32));
            mma16816(c0, c1, c2, c3, al[0][2], al[1][2], al[0][3], al[1][3],
                     (unsigned)q1, (unsigned)(q1 >> 32));
            // a_hi * b_lo
            mma16816(c0, c1, c2, c3, ah[0][0], ah[1][0], ah[0][1], ah[1][1],
                     (unsigned)q2, (unsigned)(q2 >> 32));
            mma16816(c0, c1, c2, c3, ah[0][2], ah[1][2], ah[0][3], ah[1][3],
                     (unsigned)q3, (unsigned)(q3 >> 32));
            // D rows: c0,c1 -> row gID (p0); c2,c3 -> row gID+8 (p1)
            if (o0 >= 0)
                atomicAdd((float2*)(out + (size_t)o0 * COUT + sl * 8 + 2 * tig),
                          make_float2(c0, c1));
            if (o1 >= 0)
                atomicAdd((float2*)(out + (size_t)o1 * COUT + sl * 8 + 2 * tig),
                          make_float2(c2, c3));
        }
    }
}

// ---- stats: per-channel sum / sumsq partials -------------------------------
__global__ __launch_bounds__(256) void stats_kernel(const float* __restrict__ out, int n_out)
{
    __shared__ float sh[128];
    if (threadIdx.x < 128) sh[threadIdx.x] = 0.f;
    __syncthreads();
    int gid = blockIdx.x * blockDim.x + threadIdx.x;
    int c4 = threadIdx.x & 15;
    int row0 = gid >> 4, rstride = (gridDim.x * blockDim.x) >> 4;
    const float4* o4 = (const float4*)out;
    float4 s = make_float4(0.f, 0.f, 0.f, 0.f), q = make_float4(0.f, 0.f, 0.f, 0.f);
    for (int r = row0; r < n_out; r += rstride) {
        float4 v = o4[(size_t)r * 16 + c4];
        s.x += v.x; s.y += v.y; s.z += v.z; s.w += v.w;
        q.x += v.x * v.x; q.y += v.y * v.y; q.z += v.z * v.z; q.w += v.w * v.w;
    }
    s.x += __shfl_down_sync(0xFFFFFFFFu, s.x, 16);
    s.y += __shfl_down_sync(0xFFFFFFFFu, s.y, 16);
    s.z += __shfl_down_sync(0xFFFFFFFFu, s.z, 16);
    s.w += __shfl_down_sync(0xFFFFFFFFu, s.w, 16);
    q.x += __shfl_down_sync(0xFFFFFFFFu, q.x, 16);
    q.y += __shfl_down_sync(0xFFFFFFFFu, q.y, 16);
    q.z += __shfl_down_sync(0xFFFFFFFFu, q.z, 16);
    q.w += __shfl_down_sync(0xFFFFFFFFu, q.w, 16);
    if ((threadIdx.x & 31) < 16) {
        atomicAdd(&sh[c4 * 4 + 0], s.x); atomicAdd(&sh[c4 * 4 + 1], s.y);
        atomicAdd(&sh[c4 * 4 + 2], s.z); atomicAdd(&sh[c4 * 4 + 3], s.w);
        atomicAdd(&sh[64 + c4 * 4 + 0], q.x); atomicAdd(&sh[64 + c4 * 4 + 1], q.y);
        atomicAdd(&sh[64 + c4 * 4 + 2], q.z); atomicAdd(&sh[64 + c4 * 4 + 3], q.w);
    }
    __syncthreads();
    if (threadIdx.x < 128) g_partials[blockIdx.x * 128 + threadIdx.x] = sh[threadIdx.x];
}

// ---- reduce partials (parallel over 128 stat slots) ------------------------
__global__ __launch_bounds__(256) void reduce_kernel()
{
    int s = blockIdx.x;
    float acc = 0.f;
    for (int b = threadIdx.x; b < STATS_BLOCKS; b += 256) acc += g_partials[b * 128 + s];
    __shared__ float sh[256];
    sh[threadIdx.x] = acc;
    __syncthreads();
    for (int st = 128; st > 0; st >>= 1) {
        if (threadIdx.x < st) sh[threadIdx.x] += sh[threadIdx.x + st];
        __syncthreads();
    }
    if (threadIdx.x == 0) g_tot[s] = sh[0];
}

// ---- coef: per-channel A,B -------------------------------------------------
__global__ void coef2_kernel(const float* __restrict__ gamma,
                             const float* __restrict__ beta, int n_out)
{
    int t = threadIdx.x;   // 0..63
    float inv_n = 1.0f / (float)n_out;
    float mean = g_tot[t] * inv_n;
    float var = g_tot[64 + t] * inv_n - mean * mean;
    float A = gamma[t] * rsqrtf(var + EPS);
    g_coef[t] = A;
    g_coef[64 + t] = beta[t] - mean * A;
}

// ---- norm + leaky relu (in place, at DRAM roofline) ------------------------
__global__ __launch_bounds__(256) void norm_kernel(float* __restrict__ out, int n_out)
{
    int gid = blockIdx.x * blockDim.x + threadIdx.x;
    int c4 = threadIdx.x & 15;
    const float4* cf = (const float4*)g_coef;
    float4 A = cf[c4], B = cf[16 + c4];
    int row0 = gid >> 4, rstride = (gridDim.x * blockDim.x) >> 4;
    float4* o4 = (float4*)out;
    for (int r = row0; r < n_out; r += rstride) {
        size_t idx = (size_t)r * 16 + c4;
        float4 v = o4[idx], y;
        y.x = fmaf(v.x, A.x, B.x); y.y = fmaf(v.y, A.y, B.y);
        y.z = fmaf(v.z, A.z, B.z); y.w = fmaf(v.w, A.w, B.w);
        y.x = fmaxf(y.x, LEAK * y.x); y.y = fmaxf(y.y, LEAK * y.y);
        y.z = fmaxf(y.z, LEAK * y.z); y.w = fmaxf(y.w, LEAK * y.w);
        o4[idx] = y;
    }
}

// ---- launch ----------------------------------------------------------------
extern "C" void kernel_launch(void* const* d_in, const int* in_sizes, int n_in,
                              void* d_out, int out_size)
{
    const float* feat     = (const float*)d_in[0];
    const float* weight   = (const float*)d_in[1];
    // d_in[2] = bias: cancelled exactly by BN mean subtraction
    const float* gamma    = (const float*)d_in[3];
    const float* beta     = (const float*)d_in[4];
    const int*   out_idx  = (const int*)d_in[5];
    const int*   kern_idx = (const int*)d_in[6];
    int n_rows = in_sizes[0] / CIN;
    int n_out  = out_size / COUT;
    float* out = (float*)d_out;

    cudaMemsetAsync(d_out, 0, (size_t)out_size * sizeof(float));
    hist_kernel<<<HB, 256>>>(kern_idx, n_rows);
    scan_kernel<<<1, 4 * HB>>>(n_rows);
    scatter_kernel<<<HB, 256>>>(kern_idx, n_rows);
    conv_mma<<<CONV_BLOCKS, 256>>>(feat, weight, out_idx, out);  // 5th launch -> ncu slot
    stats_kernel<<<STATS_BLOCKS, 256>>>(out, n_out);
    reduce_kernel<<<128, 256>>>();
    coef2_kernel<<<1, 64>>>(gamma, beta, n_out);
    norm_kernel<<<1184, 256>>>(out, n_out);
}

// round 17
// speedup vs baseline: 1.4652x; 1.0054x over previous
#include <cuda_runtime.h>
#include <cuda_bf16.h>
#include <cstdint>

#define CIN 32
#define COUT 64
#define EPS 1e-4f
#define LEAK 0.333f
#define HB 256
#define N_MAX 1600000
#define CONV_BLOCKS 592            // multiple of 4; k = blockIdx.x & 3
#define STATS_BLOCKS 1184

__device__ int   g_blockhist[4 * HB];
__device__ int   g_blockoff[4 * HB];
__device__ int   g_bucket_start[5];
__device__ int   g_perm[N_MAX];
__device__ float g_partials[STATS_BLOCKS * 128];
__device__ float g_tot[128];
__device__ float g_coef[128];

// pack two f32 -> bf16x2, low16 = bf16(lo), high16 = bf16(hi)
__device__ __forceinline__ unsigned bf2(float lo, float hi) {
    unsigned r;
    asm("cvt.rn.bf16x2.f32 %0, %1, %2;" : "=r"(r) : "f"(hi), "f"(lo));
    return r;
}
// split a float2 into hi bf16x2 and residual-lo bf16x2
__device__ __forceinline__ void split2(float2 v, unsigned& hi, unsigned& lo) {
    hi = bf2(v.x, v.y);
    float hx = __uint_as_float(hi << 16);
    float hy = __uint_as_float(hi & 0xFFFF0000u);
    lo = bf2(v.x - hx, v.y - hy);
}
__device__ __forceinline__ void mma16816(float& c0, float& c1, float& c2, float& c3,
                                         unsigned a0, unsigned a1, unsigned a2, unsigned a3,
                                         unsigned b0, unsigned b1) {
    asm volatile("mma.sync.aligned.m16n8k16.row.col.f32.bf16.bf16.f32 "
                 "{%0,%1,%2,%3}, {%4,%5,%6,%7}, {%8,%9}, {%0,%1,%2,%3};"
                 : "+f"(c0), "+f"(c1), "+f"(c2), "+f"(c3)
                 : "r"(a0), "r"(a1), "r"(a2), "r"(a3), "r"(b0), "r"(b1));
}

// ---- sort pass 1: per-block histogram of kern_idx --------------------------
__global__ __launch_bounds__(256) void hist_kernel(const int* __restrict__ kern_idx, int n_rows)
{
    __shared__ int cnt[4];
    if (threadIdx.x < 4) cnt[threadIdx.x] = 0;
    __syncthreads();
    int chunk = (n_rows + HB - 1) / HB;
    int i0 = blockIdx.x * chunk, i1 = min(i0 + chunk, n_rows);
    int c[4] = {0, 0, 0, 0};
    for (int i = i0 + threadIdx.x; i < i1; i += 256) c[kern_idx[i]]++;
    #pragma unroll
    for (int kk = 0; kk < 4; kk++)
        if (c[kk]) atomicAdd(&cnt[kk], c[kk]);
    __syncthreads();
    if (threadIdx.x < 4) g_blockhist[threadIdx.x * HB + blockIdx.x] = cnt[threadIdx.x];
}

// ---- sort pass 2: segmented scan -> per-block offsets + bucket starts ------
__global__ void scan_kernel(int n_rows)
{
    __shared__ int sh[4 * HB];
    int t = threadIdx.x;
    int orig = g_blockhist[t];
    sh[t] = orig;
    __syncthreads();
    for (int s = 1; s < HB; s <<= 1) {
        int add = ((t & (HB - 1)) >= s) ? sh[t - s] : 0;
        __syncthreads();
        sh[t] += add;
        __syncthreads();
    }
    int k = t >> 8, kbase = 0;
    for (int kk = 0; kk < k; kk++) kbase += sh[kk * HB + HB - 1];
    g_blockoff[t] = kbase + (sh[t] - orig);
    if ((t & (HB - 1)) == 0) g_bucket_start[k] = kbase;
    if (t == 0) g_bucket_start[4] = n_rows;
}

// ---- sort pass 3: scatter row indices into buckets -------------------------
__global__ __launch_bounds__(256) void scatter_kernel(const int* __restrict__ kern_idx, int n_rows)
{
    __shared__ int scur[4];
    if (threadIdx.x < 4) scur[threadIdx.x] = g_blockoff[threadIdx.x * HB + blockIdx.x];
    __syncthreads();
    int chunk = (n_rows + HB - 1) / HB;
    int i0 = blockIdx.x * chunk, i1 = min(i0 + chunk, n_rows);
    int iters = (i1 > i0) ? ((i1 - i0 + 255) >> 8) : 0;
    int lane = threadIdx.x & 31;
    for (int it = 0; it < iters; it++) {
        int i = i0 + it * 256 + threadIdx.x;
        int k = (i < i1) ? kern_idx[i] : -1;
        #pragma unroll
        for (int kk = 0; kk < 4; kk++) {
            unsigned mask = __ballot_sync(0xFFFFFFFFu, k == kk);
            if (k == kk) {
                int leader = __ffs(mask) - 1, base = 0;
                if (lane == leader) base = atomicAdd(&scur[kk], __popc(mask));
                base = __shfl_sync(mask, base, leader);
                g_perm[base + __popc(mask & ((1u << lane) - 1))] = i;
            }
        }
    }
}

// ---- conv via HMMA mma.sync (bf16 two-term split, K-stack 96) --------------
// Block owns bucket k = blockIdx.x & 3. Warp processes 16 rows/iter:
// lane(gID,tig) gathers its A-fragment elements directly (8 LDG.64),
// converts to hi/lo bf16x2, then 8 n-slices x 6 HMMA + 2 predicated RED.64.
// B fragments precomputed once into smem (4 unique pairs per slice).
__global__ __launch_bounds__(256) void conv_mma(
    const float* __restrict__ feat,
    const float* __restrict__ weight,
    const int*   __restrict__ out_idx,
    float*       __restrict__ out)
{
    __shared__ unsigned long long Bs[8][4][32];  // [slice][bh0,bh1,bl0,bl1][lane]
    int t = threadIdx.x;
    int lane = t & 31;
    int gID = lane >> 2, tig = lane & 3;
    int k = blockIdx.x & 3;

    // ---- precompute B fragments (once) ----
    {
        int slice = t >> 5;
        int n = slice * 8 + gID;
        #pragma unroll
        for (int pid = 0; pid < 2; pid++) {        // j-base 0 / 16
            int jb = pid * 16 + 2 * tig;
            float w00 = weight[(size_t)(k * 32 + jb) * COUT + n];
            float w01 = weight[(size_t)(k * 32 + jb + 1) * COUT + n];
            float w08 = weight[(size_t)(k * 32 + jb + 8) * COUT + n];
            float w09 = weight[(size_t)(k * 32 + jb + 9) * COUT + n];
            unsigned h0, l0, h1, l1;
            split2(make_float2(w00, w01), h0, l0);
            split2(make_float2(w08, w09), h1, l1);
            Bs[slice][pid][lane]     = ((unsigned long long)h1 << 32) | h0;
            Bs[slice][2 + pid][lane] = ((unsigned long long)l1 << 32) | l0;
        }
    }
    __syncthreads();

    int start = g_bucket_start[k], end = g_bucket_start[k + 1];
    int wid = t >> 5;
    int wslot = (blockIdx.x >> 2) * 8 + wid;
    int nwb = ((int)gridDim.x >> 2) * 8;          // warps per bucket

    for (int p = start + wslot * 16; p < end; p += nwb * 16) {
        int p0 = p + gID, p1 = p + 8 + gID;
        int pc0 = p0 < end ? p0 : end - 1;
        int pc1 = p1 < end ? p1 : end - 1;
        int i0 = g_perm[pc0], i1 = g_perm[pc1];
        int o0 = (p0 < end) ? out_idx[i0] : -1;
        int o1 = (p1 < end) ? out_idx[i1] : -1;
        const float2* f0 = (const float2*)(feat + (size_t)i0 * CIN);
        const float2* f1 = (const float2*)(feat + (size_t)i1 * CIN);

        // A fragments: rows gID (ah/al[0]) and gID+8 (ah/al[1]);
        // q-th pair = features j in {2tig, 2tig+1} + 8q
        unsigned ah[2][4], al[2][4];
        #pragma unroll
        for (int q = 0; q < 4; q++) split2(f0[tig + 4 * q], ah[0][q], al[0][q]);
        #pragma unroll
        for (int q = 0; q < 4; q++) split2(f1[tig + 4 * q], ah[1][q], al[1][q]);

        #pragma unroll
        for (int sl = 0; sl < 8; sl++) {
            unsigned long long q0 = Bs[sl][0][lane];   // b_hi j0-15
            unsigned long long q1 = Bs[sl][1][lane];   // b_hi j16-31
            unsigned long long q2 = Bs[sl][2][lane];   // b_lo j0-15
            unsigned long long q3 = Bs[sl][3][lane];   // b_lo j16-31
            float c0 = 0.f, c1 = 0.f, c2 = 0.f, c3 = 0.f;
            // a_hi * b_hi
            mma16816(c0, c1, c2, c3, ah[0][0], ah[1][0], ah[0][1], ah[1][1],
                     (unsigned)q0, (unsigned)(q0 >> 32));
            mma16816(c0, c1, c2, c3, ah[0][2], ah[1][2], ah[0][3], ah[1][3],
                     (unsigned)q1, (unsigned)(q1 >> 32));
            // a_lo * b_hi
            mma16816(c0, c1, c2, c3, al[0][0], al[1][0], al[0][1], al[1][1],
                     (unsigned)q0, (unsigned)(q0 >> 32));
            mma16816(c0, c1, c2, c3, al[0][2], al[1][2], al[0][3], al[1][3],
                     (unsigned)q1, (unsigned)(q1 >> 32));
            // a_hi * b_lo
            mma16816(c0, c1, c2, c3, ah[0][0], ah[1][0], ah[0][1], ah[1][1],
                     (unsigned)q2, (unsigned)(q2 >> 32));
            mma16816(c0, c1, c2, c3, ah[0][2], ah[1][2], ah[0][3], ah[1][3],
                     (unsigned)q3, (unsigned)(q3 >> 32));
            // D rows: c0,c1 -> row gID (p0); c2,c3 -> row gID+8 (p1)
            if (o0 >= 0)
                atomicAdd((float2*)(out + (size_t)o0 * COUT + sl * 8 + 2 * tig),
                          make_float2(c0, c1));
            if (o1 >= 0)
                atomicAdd((float2*)(out + (size_t)o1 * COUT + sl * 8 + 2 * tig),
                          make_float2(c2, c3));
        }
    }
}

// ---- stats: per-channel sum / sumsq partials -------------------------------
__global__ __launch_bounds__(256) void stats_kernel(const float* __restrict__ out, int n_out)
{
    __shared__ float sh[128];
    if (threadIdx.x < 128) sh[threadIdx.x] = 0.f;
    __syncthreads();
    int gid = blockIdx.x * blockDim.x + threadIdx.x;
    int c4 = threadIdx.x & 15;
    int row0 = gid >> 4, rstride = (gridDim.x * blockDim.x) >> 4;
    const float4* o4 = (const float4*)out;
    float4 s = make_float4(0.f, 0.f, 0.f, 0.f), q = make_float4(0.f, 0.f, 0.f, 0.f);
    for (int r = row0; r < n_out; r += rstride) {
        float4 v = o4[(size_t)r * 16 + c4];
        s.x += v.x; s.y += v.y; s.z += v.z; s.w += v.w;
        q.x += v.x * v.x; q.y += v.y * v.y; q.z += v.z * v.z; q.w += v.w * v.w;
    }
    s.x += __shfl_down_sync(0xFFFFFFFFu, s.x, 16);
    s.y += __shfl_down_sync(0xFFFFFFFFu, s.y, 16);
    s.z += __shfl_down_sync(0xFFFFFFFFu, s.z, 16);
    s.w += __shfl_down_sync(0xFFFFFFFFu, s.w, 16);
    q.x += __shfl_down_sync(0xFFFFFFFFu, q.x, 16);
    q.y += __shfl_down_sync(0xFFFFFFFFu, q.y, 16);
    q.z += __shfl_down_sync(0xFFFFFFFFu, q.z, 16);
    q.w += __shfl_down_sync(0xFFFFFFFFu, q.w, 16);
    if ((threadIdx.x & 31) < 16) {
        atomicAdd(&sh[c4 * 4 + 0], s.x); atomicAdd(&sh[c4 * 4 + 1], s.y);
        atomicAdd(&sh[c4 * 4 + 2], s.z); atomicAdd(&sh[c4 * 4 + 3], s.w);
        atomicAdd(&sh[64 + c4 * 4 + 0], q.x); atomicAdd(&sh[64 + c4 * 4 + 1], q.y);
        atomicAdd(&sh[64 + c4 * 4 + 2], q.z); atomicAdd(&sh[64 + c4 * 4 + 3], q.w);
    }
    __syncthreads();
    if (threadIdx.x < 128) g_partials[blockIdx.x * 128 + threadIdx.x] = sh[threadIdx.x];
}

// ---- reduce partials (parallel over 128 stat slots) ------------------------
__global__ __launch_bounds__(256) void reduce_kernel()
{
    int s = blockIdx.x;
    float acc = 0.f;
    for (int b = threadIdx.x; b < STATS_BLOCKS; b += 256) acc += g_partials[b * 128 + s];
    __shared__ float sh[256];
    sh[threadIdx.x] = acc;
    __syncthreads();
    for (int st = 128; st > 0; st >>= 1) {
        if (threadIdx.x < st) sh[threadIdx.x] += sh[threadIdx.x + st];
        __syncthreads();
    }
    if (threadIdx.x == 0) g_tot[s] = sh[0];
}

// ---- coef: per-channel A,B -------------------------------------------------
__global__ void coef2_kernel(const float* __restrict__ gamma,
                             const float* __restrict__ beta, int n_out)
{
    int t = threadIdx.x;   // 0..63
    float inv_n = 1.0f / (float)n_out;
    float mean = g_tot[t] * inv_n;
    float var = g_tot[64 + t] * inv_n - mean * mean;
    float A = gamma[t] * rsqrtf(var + EPS);
    g_coef[t] = A;
    g_coef[64 + t] = beta[t] - mean * A;
}

// ---- norm + leaky relu (in place, at DRAM roofline) ------------------------
__global__ __launch_bounds__(256) void norm_kernel(float* __restrict__ out, int n_out)
{
    int gid = blockIdx.x * blockDim.x + threadIdx.x;
    int c4 = threadIdx.x & 15;
    const float4* cf = (const float4*)g_coef;
    float4 A = cf[c4], B = cf[16 + c4];
    int row0 = gid >> 4, rstride = (gridDim.x * blockDim.x) >> 4;
    float4* o4 = (float4*)out;
    for (int r = row0; r < n_out; r += rstride) {
        size_t idx = (size_t)r * 16 + c4;
        float4 v = o4[idx], y;
        y.x = fmaf(v.x, A.x, B.x); y.y = fmaf(v.y, A.y, B.y);
        y.z = fmaf(v.z, A.z, B.z); y.w = fmaf(v.w, A.w, B.w);
        y.x = fmaxf(y.x, LEAK * y.x); y.y = fmaxf(y.y, LEAK * y.y);
        y.z = fmaxf(y.z, LEAK * y.z); y.w = fmaxf(y.w, LEAK * y.w);
        o4[idx] = y;
    }
}

// ---- launch ----------------------------------------------------------------
extern "C" void kernel_launch(void* const* d_in, const int* in_sizes, int n_in,
                              void* d_out, int out_size)
{
    const float* feat     = (const float*)d_in[0];
    const float* weight   = (const float*)d_in[1];
    // d_in[2] = bias: cancelled exactly by BN mean subtraction
    const float* gamma    = (const float*)d_in[3];
    const float* beta     = (const float*)d_in[4];
    const int*   out_idx  = (const int*)d_in[5];
    const int*   kern_idx = (const int*)d_in[6];
    int n_rows = in_sizes[0] / CIN;
    int n_out  = out_size / COUT;
    float* out = (float*)d_out;

    cudaMemsetAsync(d_out, 0, (size_t)out_size * sizeof(float));
    hist_kernel<<<HB, 256>>>(kern_idx, n_rows);
    scan_kernel<<<1, 4 * HB>>>(n_rows);
    scatter_kernel<<<HB, 256>>>(kern_idx, n_rows);
    conv_mma<<<CONV_BLOCKS, 256>>>(feat, weight, out_idx, out);  // 5th launch -> ncu slot
    stats_kernel<<<STATS_BLOCKS, 256>>>(out, n_out);
    reduce_kernel<<<128, 256>>>();
    coef2_kernel<<<1, 64>>>(gamma, beta, n_out);
    norm_kernel<<<1184, 256>>>(out, n_out);
}